// round 5
// baseline (speedup 1.0000x reference)
#include <cuda_runtime.h>
#include <cuda_bf16.h>
#include <math.h>
#include <stdint.h>

#define Bq 2
#define Sq 2048
#define Dq 1024
#define Hq 16
#define DHq 64
#define Mq (Bq*Sq)
#define NELEM (Mq*Dq)
#define OUT_OFF ((size_t)Mq*Dq)

typedef __nv_bfloat16 bf16;
typedef __nv_bfloat162 bf162;

// ---------------- global scratch (no allocs allowed) ----------------
__device__ __align__(16) bf16 g_wh[4][Dq*Dq];
__device__ __align__(16) bf16 g_wl[4][Dq*Dq];
__device__ __align__(16) bf16 g_xh[3][NELEM];
__device__ __align__(16) bf16 g_xl[3][NELEM];
__device__ __align__(16) bf16 g_qh[NELEM], g_ql[NELEM];
__device__ __align__(16) bf16 g_kh[NELEM], g_kl[NELEM];
__device__ __align__(16) bf16 g_vh[NELEM], g_vl[NELEM];
__device__ __align__(16) bf16 g_ch[NELEM], g_cl[NELEM];
__device__ float g_y[NELEM];

// ---------------- helpers ----------------
__device__ __forceinline__ uint32_t s2u(const void* p){ return (uint32_t)__cvta_generic_to_shared(p); }
__device__ __forceinline__ void cpa16(uint32_t s, const void* g){
    asm volatile("cp.async.cg.shared.global [%0], [%1], 16;\n" :: "r"(s), "l"(g));
}
__device__ __forceinline__ void cpcommit(){ asm volatile("cp.async.commit_group;\n" ::: "memory"); }
__device__ __forceinline__ void cpwait(){ asm volatile("cp.async.wait_group 0;\n" ::: "memory"); }
__device__ __forceinline__ void ldm4(uint32_t a, uint32_t&r0,uint32_t&r1,uint32_t&r2,uint32_t&r3){
    asm volatile("ldmatrix.sync.aligned.m8n8.x4.shared.b16 {%0,%1,%2,%3}, [%4];\n"
        : "=r"(r0),"=r"(r1),"=r"(r2),"=r"(r3) : "r"(a));
}
__device__ __forceinline__ void ldm4t(uint32_t a, uint32_t&r0,uint32_t&r1,uint32_t&r2,uint32_t&r3){
    asm volatile("ldmatrix.sync.aligned.m8n8.x4.trans.shared.b16 {%0,%1,%2,%3}, [%4];\n"
        : "=r"(r0),"=r"(r1),"=r"(r2),"=r"(r3) : "r"(a));
}
__device__ __forceinline__ void mma16(float* c, uint32_t a0,uint32_t a1,uint32_t a2,uint32_t a3,
                                      uint32_t b0,uint32_t b1){
    asm volatile("mma.sync.aligned.m16n8k16.row.col.f32.bf16.bf16.f32 "
        "{%0,%1,%2,%3}, {%4,%5,%6,%7}, {%8,%9}, {%0,%1,%2,%3};\n"
        : "+f"(c[0]),"+f"(c[1]),"+f"(c[2]),"+f"(c[3])
        : "r"(a0),"r"(a1),"r"(a2),"r"(a3),"r"(b0),"r"(b1));
}
__device__ __forceinline__ void split2(float x, bf16& h, bf16& l){
    h = __float2bfloat16(x);
    l = __float2bfloat16(x - __bfloat162float(h));
}

// ---------------- prep: split f32 -> bf16 hi/lo ----------------
__global__ void split_kernel(const float* __restrict__ x, bf16* __restrict__ ho,
                             bf16* __restrict__ lo, int n4)
{
    int i = blockIdx.x*blockDim.x + threadIdx.x;
    if (i >= n4) return;
    float4 v = reinterpret_cast<const float4*>(x)[i];
    bf16 h0,l0,h1,l1,h2,l2,h3,l3;
    split2(v.x,h0,l0); split2(v.y,h1,l1); split2(v.z,h2,l2); split2(v.w,h3,l3);
    reinterpret_cast<bf162*>(ho)[2*i+0] = __halves2bfloat162(h0,h1);
    reinterpret_cast<bf162*>(ho)[2*i+1] = __halves2bfloat162(h2,h3);
    reinterpret_cast<bf162*>(lo)[2*i+0] = __halves2bfloat162(l0,l1);
    reinterpret_cast<bf162*>(lo)[2*i+1] = __halves2bfloat162(l2,l3);
}

// ============================================================
// Shared 128x128 GEMM core (NT) for projections: bf16x3 split.
// ============================================================
template<int KT>
__device__ __forceinline__ void gemm_core(
    const bf16* __restrict__ Ahg, const bf16* __restrict__ Alg,
    const bf16* __restrict__ Bhg, const bf16* __restrict__ Blg,
    int bm, int bn, char* smem, float acc[4][4][4])
{
    const int tid = threadIdx.x;
    const int lane = tid & 31, warp = tid >> 5;
    const int wm = (warp>>2)*64, wn = (warp&3)*32;
    const uint32_t sb = s2u(smem);
    const int row = tid>>1, hf = tid&1;

    {
        uint32_t s0 = sb + (uint32_t)(row*48 + hf*16);
        size_t ga = (size_t)(bm+row)*Dq + hf*8;
        size_t gb = (size_t)(bn+row)*Dq + hf*8;
        cpa16(s0 + 0,     Ahg + ga);
        cpa16(s0 + 6144,  Alg + ga);
        cpa16(s0 + 12288, Bhg + gb);
        cpa16(s0 + 18432, Blg + gb);
        cpcommit();
    }

    for (int kt = 0; kt < KT; kt++){
        cpwait();
        __syncthreads();
        if (kt+1 < KT){
            uint32_t s0 = sb + (uint32_t)(((kt+1)&1)*24576 + row*48 + hf*16);
            const int k0 = (kt+1)*16;
            size_t ga = (size_t)(bm+row)*Dq + k0 + hf*8;
            size_t gb = (size_t)(bn+row)*Dq + k0 + hf*8;
            cpa16(s0 + 0,     Ahg + ga);
            cpa16(s0 + 6144,  Alg + ga);
            cpa16(s0 + 12288, Bhg + gb);
            cpa16(s0 + 18432, Blg + gb);
            cpcommit();
        }
        const uint32_t st = sb + (uint32_t)((kt&1)*24576);
        uint32_t bhf[4][2], blf[4][2];
#pragma unroll
        for (int p = 0; p < 2; p++){
            uint32_t addr = st + 12288u +
                (uint32_t)((wn + p*16 + (lane&7) + ((lane>>4)&1)*8)*48 + ((lane>>3)&1)*16);
            ldm4(addr,        bhf[2*p][0], bhf[2*p][1], bhf[2*p+1][0], bhf[2*p+1][1]);
            ldm4(addr + 6144, blf[2*p][0], blf[2*p][1], blf[2*p+1][0], blf[2*p+1][1]);
        }
#pragma unroll
        for (int mi = 0; mi < 4; mi++){
            uint32_t aaddr = st + (uint32_t)((wm + mi*16 + (lane&15))*48 + ((lane>>4)&1)*16);
            uint32_t a0,a1,a2,a3, l0,l1,l2,l3;
            ldm4(aaddr,        a0,a1,a2,a3);
            ldm4(aaddr + 6144, l0,l1,l2,l3);
#pragma unroll
            for (int ni = 0; ni < 4; ni++){
                mma16(acc[mi][ni], a0,a1,a2,a3, bhf[ni][0], bhf[ni][1]);
                mma16(acc[mi][ni], a0,a1,a2,a3, blf[ni][0], blf[ni][1]);
                mma16(acc[mi][ni], l0,l1,l2,l3, bhf[ni][0], bhf[ni][1]);
            }
        }
    }
}

// ============================================================
// Projection: C = A*W^T + bias (+resid). Split-out (q/k/v) or f32-out (O).
// ============================================================
__global__ __launch_bounds__(256,2) void proj_kernel(
    const bf16* __restrict__ Ahg, const bf16* __restrict__ Alg,
    const bf16* __restrict__ Bhg, const bf16* __restrict__ Blg,
    const float* __restrict__ bias, const float* __restrict__ resid,
    bf16* __restrict__ outh, bf16* __restrict__ outl, float* __restrict__ outf)
{
    __shared__ char smem[49152];
    float acc[4][4][4] = {};
    const int bm = blockIdx.y*128, bn = blockIdx.x*128;
    gemm_core<64>(Ahg,Alg,Bhg,Blg,bm,bn,smem,acc);

    const int lane = threadIdx.x & 31, warp = threadIdx.x>>5;
    const int wm=(warp>>2)*64, wn=(warp&3)*32, g=lane>>2, tg=lane&3;
#pragma unroll
    for (int mi=0; mi<4; mi++)
#pragma unroll
    for (int ni=0; ni<4; ni++){
        const int r0 = bm+wm+mi*16+g;
        const int c  = bn+wn+ni*8+tg*2;
        const float2 bv = *reinterpret_cast<const float2*>(&bias[c]);
        const float x0=acc[mi][ni][0]+bv.x, x1=acc[mi][ni][1]+bv.y;
        const float x2=acc[mi][ni][2]+bv.x, x3=acc[mi][ni][3]+bv.y;
        if (outf){
            const float2 q0 = *reinterpret_cast<const float2*>(&resid[(size_t)r0*Dq + c]);
            const float2 q1 = *reinterpret_cast<const float2*>(&resid[(size_t)(r0+8)*Dq + c]);
            *reinterpret_cast<float2*>(&outf[(size_t)r0*Dq+c])     = make_float2(x0+q0.x, x1+q0.y);
            *reinterpret_cast<float2*>(&outf[(size_t)(r0+8)*Dq+c]) = make_float2(x2+q1.x, x3+q1.y);
        } else {
            bf16 h0,l0,h1,l1;
            split2(x0,h0,l0); split2(x1,h1,l1);
            *reinterpret_cast<bf162*>(&outh[(size_t)r0*Dq+c]) = __halves2bfloat162(h0,h1);
            *reinterpret_cast<bf162*>(&outl[(size_t)r0*Dq+c]) = __halves2bfloat162(l0,l1);
            split2(x2,h0,l0); split2(x3,h1,l1);
            *reinterpret_cast<bf162*>(&outh[(size_t)(r0+8)*Dq+c]) = __halves2bfloat162(h0,h1);
            *reinterpret_cast<bf162*>(&outl[(size_t)(r0+8)*Dq+c]) = __halves2bfloat162(l0,l1);
        }
    }
}

// ============================================================
// FUSED scores + softmax. CTA = 16 q-rows x 2048 keys for one (b,h).
// S strip lives in smem (16 x 2052 f32), K streamed via cp.async,
// softmax done in smem, final P written to d_out ONCE.
// smem: S 131328 | Q 4608 (hi 2304 + lo 2304, pitch 144) |
//       K 2 stages x 36864 (hi 18432 + lo 18432, pitch 144)
// ============================================================
#define QT 16
#define SPITCH 2052
#define SMS_S 0
#define SMS_Q 131328
#define SMS_K 135936
#define KSTAGE 36864
#define SMS_TOT (SMS_K + 2*KSTAGE)   // 209664

__global__ __launch_bounds__(256,1) void scores_softmax_kernel(float* __restrict__ scores)
{
    extern __shared__ char sm[];
    const int bh = blockIdx.y, b = bh>>4, h = bh&15;
    const int bm = blockIdx.x * QT;
    const bf16* Qhg = g_qh + ((size_t)b*Sq + bm)*Dq + h*DHq;
    const bf16* Qlg = g_ql + ((size_t)b*Sq + bm)*Dq + h*DHq;
    const bf16* Khg = g_kh + (size_t)b*Sq*Dq + h*DHq;
    const bf16* Klg = g_kl + (size_t)b*Sq*Dq + h*DHq;
    float* C = scores + (size_t)bh*Sq*Sq + (size_t)bm*Sq;

    const int tid = threadIdx.x, lane = tid & 31, warp = tid >> 5;
    const uint32_t sb = s2u(sm);

    // ---- load Q tile (16 x 64, hi+lo) : one 16B chunk per thread ----
    {
        const int part = tid>>7, idx = tid&127, row = idx>>3, c16 = idx&7;
        const bf16* src = part ? Qlg : Qhg;
        cpa16(sb + SMS_Q + (uint32_t)(part*2304 + row*144 + c16*16),
              src + (size_t)row*Dq + c16*8);
        cpcommit();
    }
    // ---- prologue: K tile 0 ----
    {
#pragma unroll
        for (int r = 0; r < 8; r++){
            const int i = tid + r*256;
            const int part = i>>10, idx = i&1023, row = idx>>3, c = idx&7;
            const bf16* src = part ? Klg : Khg;
            cpa16(sb + SMS_K + (uint32_t)(part*18432 + row*144 + c*16),
                  src + (size_t)row*Dq + c*8);
        }
        cpcommit();
    }
    cpwait();
    __syncthreads();

    // ---- persistent Q frags ----
    uint32_t qh[4][4], ql[4][4];
#pragma unroll
    for (int ks = 0; ks < 4; ks++){
        uint32_t qa = sb + SMS_Q + (uint32_t)((lane&15)*144 + ks*32 + (lane>>4)*16);
        ldm4(qa,        qh[ks][0],qh[ks][1],qh[ks][2],qh[ks][3]);
        ldm4(qa + 2304, ql[ks][0],ql[ks][1],ql[ks][2],ql[ks][3]);
    }

    const int nb = warp*16;
    const int g = lane>>2, tg = lane&3;
    float* Sf = reinterpret_cast<float*>(sm);

    for (int t = 0; t < 16; t++){
        if (t > 0){ cpwait(); __syncthreads(); }
        if (t+1 < 16){
            const uint32_t ksb = sb + SMS_K + (uint32_t)(((t+1)&1)*KSTAGE);
#pragma unroll
            for (int r = 0; r < 8; r++){
                const int i = tid + r*256;
                const int part = i>>10, idx = i&1023, row = idx>>3, c = idx&7;
                const bf16* src = part ? Klg : Khg;
                cpa16(ksb + (uint32_t)(part*18432 + row*144 + c*16),
                      src + (size_t)((t+1)*128 + row)*Dq + c*8);
            }
            cpcommit();
        }
        const uint32_t kst = sb + SMS_K + (uint32_t)((t&1)*KSTAGE);
        float acc[2][4] = {};
#pragma unroll
        for (int ks = 0; ks < 4; ks++){
            uint32_t b0,b1,b2,b3, c0,c1,c2,c3;
            uint32_t ba = kst + (uint32_t)((nb + (lane&7) + ((lane>>4)&1)*8)*144
                                           + ks*32 + ((lane>>3)&1)*16);
            ldm4(ba,         b0,b1,b2,b3);
            ldm4(ba + 18432, c0,c1,c2,c3);
            mma16(acc[0], qh[ks][0],qh[ks][1],qh[ks][2],qh[ks][3], b0,b1);
            mma16(acc[0], qh[ks][0],qh[ks][1],qh[ks][2],qh[ks][3], c0,c1);
            mma16(acc[0], ql[ks][0],ql[ks][1],ql[ks][2],ql[ks][3], b0,b1);
            mma16(acc[1], qh[ks][0],qh[ks][1],qh[ks][2],qh[ks][3], b2,b3);
            mma16(acc[1], qh[ks][0],qh[ks][1],qh[ks][2],qh[ks][3], c2,c3);
            mma16(acc[1], ql[ks][0],ql[ks][1],ql[ks][2],ql[ks][3], b2,b3);
        }
        // stash raw S tile into smem strip
#pragma unroll
        for (int f = 0; f < 2; f++){
            const int col = t*128 + nb + f*8 + tg*2;
            *reinterpret_cast<float2*>(&Sf[(size_t)g*SPITCH + col]) =
                make_float2(acc[f][0], acc[f][1]);
            *reinterpret_cast<float2*>(&Sf[(size_t)(g+8)*SPITCH + col]) =
                make_float2(acc[f][2], acc[f][3]);
        }
    }
    __syncthreads();

    // ---- softmax over smem strip; no max subtraction (|s|<~7 safe) ----
    const int row = tid>>4, l16 = tid&15;
    float* Sp = Sf + (size_t)row*SPITCH;
    float sum = 0.f;
#pragma unroll
    for (int j = 0; j < 32; j++){
        float4* p = reinterpret_cast<float4*>(Sp) + (l16 + 16*j);
        float4 v = *p;
        v.x = __expf(v.x*0.125f); v.y = __expf(v.y*0.125f);
        v.z = __expf(v.z*0.125f); v.w = __expf(v.w*0.125f);
        *p = v;
        sum += v.x + v.y + v.z + v.w;
    }
#pragma unroll
    for (int o = 8; o > 0; o >>= 1)
        sum += __shfl_xor_sync(0xffffffffu, sum, o);
    const float inv = 1.0f / sum;
#pragma unroll
    for (int j = 0; j < 32; j++){
        float4 v = reinterpret_cast<float4*>(Sp)[l16 + 16*j];
        v.x *= inv; v.y *= inv; v.z *= inv; v.w *= inv;
        reinterpret_cast<float4*>(&C[(size_t)row*Sq])[l16 + 16*j] = v;
    }
}

// ============================================================
// PV: ctx[q, h*64+d] = sum_k P[q,k]*V[k, h*64+d]  (split bf16 out)
// ============================================================
__global__ __launch_bounds__(256,2) void av_kernel(const float* __restrict__ scores)
{
    __shared__ char smem[2*16896];
    const int bh = blockIdx.z, b = bh>>4, h = bh&15;
    const float* P = scores + (size_t)bh*Sq*Sq;
    const bf16* Vhg = g_vh + (size_t)b*Sq*Dq + h*DHq;
    const bf16* Vlg = g_vl + (size_t)b*Sq*Dq + h*DHq;
    const int tid = threadIdx.x, lane = tid&31, warp = tid>>5;
    const int wm = (warp>>1)*32, wn = (warp&1)*32;
    const int bm = blockIdx.y*128;
    const uint32_t sb = s2u(smem);

    float acc[2][4][4] = {};

    const int va = tid>>7, vr = (tid>>3)&15, vc = tid&7;
    const bf16* vsrc = va ? Vlg : Vhg;
    const int pr = tid>>2, pq = (tid&3)*4;

    float4 p0, p1, n0, n1;
    p0 = *reinterpret_cast<const float4*>(&P[(size_t)(bm + pr)*Sq + pq]);
    p1 = *reinterpret_cast<const float4*>(&P[(size_t)(bm + 64 + pr)*Sq + pq]);
    {
        uint32_t s = sb + 12288u + (uint32_t)(va*2304 + vr*144 + vc*16);
        cpa16(s, vsrc + (size_t)vr*Dq + vc*8);
        cpcommit();
    }

    for (int kt = 0; kt < 128; kt++){
        const int s = kt&1;
        const uint32_t st = sb + (uint32_t)(s*16896);
        {
            bf16 h0,l0,h1,l1,h2,l2,h3,l3;
            char* base = smem + s*16896;
            split2(p0.x,h0,l0); split2(p0.y,h1,l1); split2(p0.z,h2,l2); split2(p0.w,h3,l3);
            *reinterpret_cast<bf162*>(base + pr*48 + pq*2)          = __halves2bfloat162(h0,h1);
            *reinterpret_cast<bf162*>(base + pr*48 + pq*2 + 4)      = __halves2bfloat162(h2,h3);
            *reinterpret_cast<bf162*>(base + 6144 + pr*48 + pq*2)   = __halves2bfloat162(l0,l1);
            *reinterpret_cast<bf162*>(base + 6144 + pr*48 + pq*2+4) = __halves2bfloat162(l2,l3);
            split2(p1.x,h0,l0); split2(p1.y,h1,l1); split2(p1.z,h2,l2); split2(p1.w,h3,l3);
            *reinterpret_cast<bf162*>(base + (pr+64)*48 + pq*2)          = __halves2bfloat162(h0,h1);
            *reinterpret_cast<bf162*>(base + (pr+64)*48 + pq*2 + 4)      = __halves2bfloat162(h2,h3);
            *reinterpret_cast<bf162*>(base + 6144 + (pr+64)*48 + pq*2)   = __halves2bfloat162(l0,l1);
            *reinterpret_cast<bf162*>(base + 6144 + (pr+64)*48 + pq*2+4) = __halves2bfloat162(l2,l3);
        }
        if (kt+1 < 128){
            const int k0 = (kt+1)*16;
            n0 = *reinterpret_cast<const float4*>(&P[(size_t)(bm + pr)*Sq + k0 + pq]);
            n1 = *reinterpret_cast<const float4*>(&P[(size_t)(bm + 64 + pr)*Sq + k0 + pq]);
        }
        cpwait();
        __syncthreads();
        if (kt+1 < 128){
            const int k0 = (kt+1)*16;
            uint32_t sv = sb + (uint32_t)((s^1)*16896) + 12288u + (uint32_t)(va*2304 + vr*144 + vc*16);
            cpa16(sv, vsrc + (size_t)(k0+vr)*Dq + vc*8);
            cpcommit();
        }
        uint32_t bhf[4][2], blf[4][2];
#pragma unroll
        for (int p = 0; p < 2; p++){
            uint32_t addr = st + 12288u +
                (uint32_t)(((lane>>3)&1)*8*144 + (lane&7)*144 + (wn + p*16 + ((lane>>4)&1)*8)*2);
            ldm4t(addr,        bhf[2*p][0], bhf[2*p][1], bhf[2*p+1][0], bhf[2*p+1][1]);
            ldm4t(addr + 2304, blf[2*p][0], blf[2*p][1], blf[2*p+1][0], blf[2*p+1][1]);
        }
#pragma unroll
        for (int mi = 0; mi < 2; mi++){
            uint32_t aaddr = st + (uint32_t)((wm + mi*16 + (lane&15))*48 + ((lane>>4)&1)*16);
            uint32_t a0,a1,a2,a3, l0,l1,l2,l3;
            ldm4(aaddr,        a0,a1,a2,a3);
            ldm4(aaddr + 6144, l0,l1,l2,l3);
#pragma unroll
            for (int ni = 0; ni < 4; ni++){
                mma16(acc[mi][ni], a0,a1,a2,a3, bhf[ni][0], bhf[ni][1]);
                mma16(acc[mi][ni], a0,a1,a2,a3, blf[ni][0], blf[ni][1]);
                mma16(acc[mi][ni], l0,l1,l2,l3, bhf[ni][0], bhf[ni][1]);
            }
        }
        p0 = n0; p1 = n1;
    }

    const int g = lane>>2, tg = lane&3;
#pragma unroll
    for (int mi = 0; mi < 2; mi++)
#pragma unroll
    for (int ni = 0; ni < 4; ni++){
        const int r0 = bm + wm + mi*16 + g;
        const int c  = wn + ni*8 + tg*2;
        const size_t i0 = (size_t)(b*Sq + r0)*Dq + h*DHq + c;
        const size_t i1 = (size_t)(b*Sq + r0 + 8)*Dq + h*DHq + c;
        bf16 h0,l0,h1,l1;
        split2(acc[mi][ni][0],h0,l0); split2(acc[mi][ni][1],h1,l1);
        *reinterpret_cast<bf162*>(&g_ch[i0]) = __halves2bfloat162(h0,h1);
        *reinterpret_cast<bf162*>(&g_cl[i0]) = __halves2bfloat162(l0,l1);
        split2(acc[mi][ni][2],h0,l0); split2(acc[mi][ni][3],h1,l1);
        *reinterpret_cast<bf162*>(&g_ch[i1]) = __halves2bfloat162(h0,h1);
        *reinterpret_cast<bf162*>(&g_cl[i1]) = __halves2bfloat162(l0,l1);
    }
}

// ============================================================
// LayerNorm per row of g_y -> d_out
// ============================================================
__global__ void ln_kernel(const float* __restrict__ gamma,
                          const float* __restrict__ beta,
                          float* __restrict__ out)
{
    const size_t row = blockIdx.x;
    const float4* y = reinterpret_cast<const float4*>(g_y + row * (size_t)Dq);
    float4* o = reinterpret_cast<float4*>(out + row * (size_t)Dq);
    const int tid = threadIdx.x;
    __shared__ float sm[8], sm2[8];

    float4 v = y[tid];
    float s  = v.x + v.y + v.z + v.w;
    float s2 = v.x*v.x + v.y*v.y + v.z*v.z + v.w*v.w;
#pragma unroll
    for (int o2 = 16; o2 > 0; o2 >>= 1) {
        s  += __shfl_xor_sync(0xffffffffu, s,  o2);
        s2 += __shfl_xor_sync(0xffffffffu, s2, o2);
    }
    if ((tid & 31) == 0) { sm[tid>>5] = s; sm2[tid>>5] = s2; }
    __syncthreads();
    float ts = 0.f, ts2 = 0.f;
#pragma unroll
    for (int w = 0; w < 8; w++) { ts += sm[w]; ts2 += sm2[w]; }
    const float mean = ts * (1.0f/Dq);
    const float var  = ts2 * (1.0f/Dq) - mean*mean;
    const float rstd = rsqrtf(var + 1e-6f);

    const float4 gg = reinterpret_cast<const float4*>(gamma)[tid];
    const float4 bb = reinterpret_cast<const float4*>(beta)[tid];
    float4 r;
    r.x = (v.x - mean) * rstd * gg.x + bb.x;
    r.y = (v.y - mean) * rstd * gg.y + bb.y;
    r.z = (v.z - mean) * rstd * gg.z + bb.z;
    r.w = (v.w - mean) * rstd * gg.w + bb.w;
    o[tid] = r;
}

// ============================================================
extern "C" void kernel_launch(void* const* d_in, const int* in_sizes, int n_in,
                              void* d_out, int out_size)
{
    const float* Q     = (const float*)d_in[0];
    const float* K     = (const float*)d_in[1];
    const float* V     = (const float*)d_in[2];
    const float* Wq    = (const float*)d_in[3];
    const float* bq    = (const float*)d_in[4];
    const float* Wk    = (const float*)d_in[5];
    const float* bk    = (const float*)d_in[6];
    const float* Wv    = (const float*)d_in[7];
    const float* bv    = (const float*)d_in[8];
    const float* Wo    = (const float*)d_in[9];
    const float* bo    = (const float*)d_in[10];
    const float* gamma = (const float*)d_in[11];
    const float* beta  = (const float*)d_in[12];

    float* out    = (float*)d_out;
    float* scores = out + OUT_OFF;

    bf16 *wh, *wl, *xh, *xl, *qh, *ql, *kh, *kl, *vh, *vl, *ch, *cl;
    float* gy;
    cudaGetSymbolAddress((void**)&wh, g_wh);
    cudaGetSymbolAddress((void**)&wl, g_wl);
    cudaGetSymbolAddress((void**)&xh, g_xh);
    cudaGetSymbolAddress((void**)&xl, g_xl);
    cudaGetSymbolAddress((void**)&qh, g_qh); cudaGetSymbolAddress((void**)&ql, g_ql);
    cudaGetSymbolAddress((void**)&kh, g_kh); cudaGetSymbolAddress((void**)&kl, g_kl);
    cudaGetSymbolAddress((void**)&vh, g_vh); cudaGetSymbolAddress((void**)&vl, g_vl);
    cudaGetSymbolAddress((void**)&ch, g_ch); cudaGetSymbolAddress((void**)&cl, g_cl);
    cudaGetSymbolAddress((void**)&gy, g_y);

    const int WN = Dq*Dq;

    // prep splits
    split_kernel<<<WN/4/256, 256>>>(Wq, wh + 0*WN, wl + 0*WN, WN/4);
    split_kernel<<<WN/4/256, 256>>>(Wk, wh + 1*WN, wl + 1*WN, WN/4);
    split_kernel<<<WN/4/256, 256>>>(Wv, wh + 2*WN, wl + 2*WN, WN/4);
    split_kernel<<<WN/4/256, 256>>>(Wo, wh + 3*WN, wl + 3*WN, WN/4);
    split_kernel<<<NELEM/4/256, 256>>>(Q, xh + 0*(size_t)NELEM, xl + 0*(size_t)NELEM, NELEM/4);
    split_kernel<<<NELEM/4/256, 256>>>(K, xh + 1*(size_t)NELEM, xl + 1*(size_t)NELEM, NELEM/4);
    split_kernel<<<NELEM/4/256, 256>>>(V, xh + 2*(size_t)NELEM, xl + 2*(size_t)NELEM, NELEM/4);

    dim3 blk(256);
    dim3 gProj(Dq/128, Mq/128);
    proj_kernel<<<gProj, blk>>>(xh+0*(size_t)NELEM, xl+0*(size_t)NELEM, wh+0*WN, wl+0*WN,
                                bq, nullptr, qh, ql, nullptr);
    proj_kernel<<<gProj, blk>>>(xh+1*(size_t)NELEM, xl+1*(size_t)NELEM, wh+1*WN, wl+1*WN,
                                bk, nullptr, kh, kl, nullptr);
    proj_kernel<<<gProj, blk>>>(xh+2*(size_t)NELEM, xl+2*(size_t)NELEM, wh+2*WN, wl+2*WN,
                                bv, nullptr, vh, vl, nullptr);

    // fused scores + softmax
    cudaFuncSetAttribute(scores_softmax_kernel,
                         cudaFuncAttributeMaxDynamicSharedMemorySize, SMS_TOT);
    dim3 gF(Sq/QT, Bq*Hq);    // (128, 32)
    scores_softmax_kernel<<<gF, blk, SMS_TOT>>>(scores);

    dim3 gAv(1, Sq/128, Bq*Hq);
    av_kernel<<<gAv, blk>>>(scores);

    proj_kernel<<<gProj, blk>>>(ch, cl, wh+3*WN, wl+3*WN, bo, Q, nullptr, nullptr, gy);

    ln_kernel<<<(unsigned)Mq, blk>>>(gamma, beta, out);
}

// round 6
// speedup vs baseline: 1.2007x; 1.2007x over previous
#include <cuda_runtime.h>
#include <cuda_bf16.h>
#include <math.h>
#include <stdint.h>

#define Bq 2
#define Sq 2048
#define Dq 1024
#define Hq 16
#define DHq 64
#define Mq (Bq*Sq)
#define NELEM (Mq*Dq)
#define OUT_OFF ((size_t)Mq*Dq)

typedef __nv_bfloat16 bf16;
typedef __nv_bfloat162 bf162;

// ---------------- global scratch (no allocs allowed) ----------------
__device__ __align__(16) bf16 g_wh[4][Dq*Dq];
__device__ __align__(16) bf16 g_wl[4][Dq*Dq];
__device__ __align__(16) bf16 g_xh[3][NELEM];
__device__ __align__(16) bf16 g_xl[3][NELEM];
__device__ __align__(16) bf16 g_qh[NELEM], g_ql[NELEM];
__device__ __align__(16) bf16 g_kh[NELEM], g_kl[NELEM];
__device__ __align__(16) bf16 g_vh[NELEM], g_vl[NELEM];
__device__ __align__(16) bf16 g_ch[NELEM], g_cl[NELEM];
__device__ float g_y[NELEM];
// partial row sums of exp(S/8): [bh][col_tile 0..15][row 0..2047]
__device__ float g_psum[(size_t)Bq*Hq*16*Sq];

// ---------------- helpers ----------------
__device__ __forceinline__ uint32_t s2u(const void* p){ return (uint32_t)__cvta_generic_to_shared(p); }
__device__ __forceinline__ void cpa16(uint32_t s, const void* g){
    asm volatile("cp.async.cg.shared.global [%0], [%1], 16;\n" :: "r"(s), "l"(g));
}
__device__ __forceinline__ void cpcommit(){ asm volatile("cp.async.commit_group;\n" ::: "memory"); }
__device__ __forceinline__ void cpwait(){ asm volatile("cp.async.wait_group 0;\n" ::: "memory"); }
__device__ __forceinline__ void ldm4(uint32_t a, uint32_t&r0,uint32_t&r1,uint32_t&r2,uint32_t&r3){
    asm volatile("ldmatrix.sync.aligned.m8n8.x4.shared.b16 {%0,%1,%2,%3}, [%4];\n"
        : "=r"(r0),"=r"(r1),"=r"(r2),"=r"(r3) : "r"(a));
}
__device__ __forceinline__ void ldm4t(uint32_t a, uint32_t&r0,uint32_t&r1,uint32_t&r2,uint32_t&r3){
    asm volatile("ldmatrix.sync.aligned.m8n8.x4.trans.shared.b16 {%0,%1,%2,%3}, [%4];\n"
        : "=r"(r0),"=r"(r1),"=r"(r2),"=r"(r3) : "r"(a));
}
__device__ __forceinline__ void mma16(float* c, uint32_t a0,uint32_t a1,uint32_t a2,uint32_t a3,
                                      uint32_t b0,uint32_t b1){
    asm volatile("mma.sync.aligned.m16n8k16.row.col.f32.bf16.bf16.f32 "
        "{%0,%1,%2,%3}, {%4,%5,%6,%7}, {%8,%9}, {%0,%1,%2,%3};\n"
        : "+f"(c[0]),"+f"(c[1]),"+f"(c[2]),"+f"(c[3])
        : "r"(a0),"r"(a1),"r"(a2),"r"(a3),"r"(b0),"r"(b1));
}
__device__ __forceinline__ void split2(float x, bf16& h, bf16& l){
    h = __float2bfloat16(x);
    l = __float2bfloat16(x - __bfloat162float(h));
}

// ---------------- prep: split f32 -> bf16 hi/lo ----------------
__global__ void split_kernel(const float* __restrict__ x, bf16* __restrict__ ho,
                             bf16* __restrict__ lo, int n4)
{
    int i = blockIdx.x*blockDim.x + threadIdx.x;
    if (i >= n4) return;
    float4 v = reinterpret_cast<const float4*>(x)[i];
    bf16 h0,l0,h1,l1,h2,l2,h3,l3;
    split2(v.x,h0,l0); split2(v.y,h1,l1); split2(v.z,h2,l2); split2(v.w,h3,l3);
    reinterpret_cast<bf162*>(ho)[2*i+0] = __halves2bfloat162(h0,h1);
    reinterpret_cast<bf162*>(ho)[2*i+1] = __halves2bfloat162(h2,h3);
    reinterpret_cast<bf162*>(lo)[2*i+0] = __halves2bfloat162(l0,l1);
    reinterpret_cast<bf162*>(lo)[2*i+1] = __halves2bfloat162(l2,l3);
}

// ============================================================
// Shared 128x128 GEMM core (NT): bf16x3 split, 2-stage cp.async.
// ============================================================
template<int KT>
__device__ __forceinline__ void gemm_core(
    const bf16* __restrict__ Ahg, const bf16* __restrict__ Alg,
    const bf16* __restrict__ Bhg, const bf16* __restrict__ Blg,
    int bm, int bn, char* smem, float acc[4][4][4])
{
    const int tid = threadIdx.x;
    const int lane = tid & 31, warp = tid >> 5;
    const int wm = (warp>>2)*64, wn = (warp&3)*32;
    const uint32_t sb = s2u(smem);
    const int row = tid>>1, hf = tid&1;

    {
        uint32_t s0 = sb + (uint32_t)(row*48 + hf*16);
        size_t ga = (size_t)(bm+row)*Dq + hf*8;
        size_t gb = (size_t)(bn+row)*Dq + hf*8;
        cpa16(s0 + 0,     Ahg + ga);
        cpa16(s0 + 6144,  Alg + ga);
        cpa16(s0 + 12288, Bhg + gb);
        cpa16(s0 + 18432, Blg + gb);
        cpcommit();
    }

    for (int kt = 0; kt < KT; kt++){
        cpwait();
        __syncthreads();
        if (kt+1 < KT){
            uint32_t s0 = sb + (uint32_t)(((kt+1)&1)*24576 + row*48 + hf*16);
            const int k0 = (kt+1)*16;
            size_t ga = (size_t)(bm+row)*Dq + k0 + hf*8;
            size_t gb = (size_t)(bn+row)*Dq + k0 + hf*8;
            cpa16(s0 + 0,     Ahg + ga);
            cpa16(s0 + 6144,  Alg + ga);
            cpa16(s0 + 12288, Bhg + gb);
            cpa16(s0 + 18432, Blg + gb);
            cpcommit();
        }
        const uint32_t st = sb + (uint32_t)((kt&1)*24576);
        uint32_t bhf[4][2], blf[4][2];
#pragma unroll
        for (int p = 0; p < 2; p++){
            uint32_t addr = st + 12288u +
                (uint32_t)((wn + p*16 + (lane&7) + ((lane>>4)&1)*8)*48 + ((lane>>3)&1)*16);
            ldm4(addr,        bhf[2*p][0], bhf[2*p][1], bhf[2*p+1][0], bhf[2*p+1][1]);
            ldm4(addr + 6144, blf[2*p][0], blf[2*p][1], blf[2*p+1][0], blf[2*p+1][1]);
        }
#pragma unroll
        for (int mi = 0; mi < 4; mi++){
            uint32_t aaddr = st + (uint32_t)((wm + mi*16 + (lane&15))*48 + ((lane>>4)&1)*16);
            uint32_t a0,a1,a2,a3, l0,l1,l2,l3;
            ldm4(aaddr,        a0,a1,a2,a3);
            ldm4(aaddr + 6144, l0,l1,l2,l3);
#pragma unroll
            for (int ni = 0; ni < 4; ni++){
                mma16(acc[mi][ni], a0,a1,a2,a3, bhf[ni][0], bhf[ni][1]);
                mma16(acc[mi][ni], a0,a1,a2,a3, blf[ni][0], blf[ni][1]);
                mma16(acc[mi][ni], l0,l1,l2,l3, bhf[ni][0], bhf[ni][1]);
            }
        }
    }
}

// ============================================================
// Projection: C = A*W^T + bias (+resid). Split-out (q/k/v) or f32-out (O).
// ============================================================
__global__ __launch_bounds__(256,2) void proj_kernel(
    const bf16* __restrict__ Ahg, const bf16* __restrict__ Alg,
    const bf16* __restrict__ Bhg, const bf16* __restrict__ Blg,
    const float* __restrict__ bias, const float* __restrict__ resid,
    bf16* __restrict__ outh, bf16* __restrict__ outl, float* __restrict__ outf)
{
    __shared__ char smem[49152];
    float acc[4][4][4] = {};
    const int bm = blockIdx.y*128, bn = blockIdx.x*128;
    gemm_core<64>(Ahg,Alg,Bhg,Blg,bm,bn,smem,acc);

    const int lane = threadIdx.x & 31, warp = threadIdx.x>>5;
    const int wm=(warp>>2)*64, wn=(warp&3)*32, g=lane>>2, tg=lane&3;
#pragma unroll
    for (int mi=0; mi<4; mi++)
#pragma unroll
    for (int ni=0; ni<4; ni++){
        const int r0 = bm+wm+mi*16+g;
        const int c  = bn+wn+ni*8+tg*2;
        const float2 bv = *reinterpret_cast<const float2*>(&bias[c]);
        const float x0=acc[mi][ni][0]+bv.x, x1=acc[mi][ni][1]+bv.y;
        const float x2=acc[mi][ni][2]+bv.x, x3=acc[mi][ni][3]+bv.y;
        if (outf){
            const float2 q0 = *reinterpret_cast<const float2*>(&resid[(size_t)r0*Dq + c]);
            const float2 q1 = *reinterpret_cast<const float2*>(&resid[(size_t)(r0+8)*Dq + c]);
            *reinterpret_cast<float2*>(&outf[(size_t)r0*Dq+c])     = make_float2(x0+q0.x, x1+q0.y);
            *reinterpret_cast<float2*>(&outf[(size_t)(r0+8)*Dq+c]) = make_float2(x2+q1.x, x3+q1.y);
        } else {
            bf16 h0,l0,h1,l1;
            split2(x0,h0,l0); split2(x1,h1,l1);
            *reinterpret_cast<bf162*>(&outh[(size_t)r0*Dq+c]) = __halves2bfloat162(h0,h1);
            *reinterpret_cast<bf162*>(&outl[(size_t)r0*Dq+c]) = __halves2bfloat162(l0,l1);
            split2(x2,h0,l0); split2(x3,h1,l1);
            *reinterpret_cast<bf162*>(&outh[(size_t)(r0+8)*Dq+c]) = __halves2bfloat162(h0,h1);
            *reinterpret_cast<bf162*>(&outl[(size_t)(r0+8)*Dq+c]) = __halves2bfloat162(l0,l1);
        }
    }
}

// ============================================================
// Scores: per (b,h) E[q,k] = exp((q.k)/8), writes E to d_out scores
// region plus deterministic per-(coltile,row) partial sums.
// ============================================================
__global__ __launch_bounds__(256,2) void scores_kernel(float* __restrict__ scores)
{
    __shared__ char smem[49152];
    const int bh = blockIdx.z, b = bh>>4, h = bh&15;
    const size_t boff = (size_t)b*Sq*Dq + h*DHq;
    float acc[4][4][4] = {};
    const int bm = blockIdx.y*128, bn = blockIdx.x*128;
    gemm_core<4>(g_qh+boff, g_ql+boff, g_kh+boff, g_kl+boff, bm, bn, smem, acc);

    __shared__ float psum[128][4];

    float* C = scores + (size_t)bh*Sq*Sq;
    const int tid = threadIdx.x;
    const int lane = tid & 31, warp = tid>>5;
    const int wm=(warp>>2)*64, wn=(warp&3)*32, g=lane>>2, tg=lane&3;
    const int wnidx = warp & 3;
#pragma unroll
    for (int mi=0; mi<4; mi++){
        float s0 = 0.f, s1 = 0.f;
#pragma unroll
        for (int ni=0; ni<4; ni++){
            const int r0 = bm+wm+mi*16+g;
            const int c  = bn+wn+ni*8+tg*2;
            const float e0 = __expf(acc[mi][ni][0]*0.125f);
            const float e1 = __expf(acc[mi][ni][1]*0.125f);
            const float e2 = __expf(acc[mi][ni][2]*0.125f);
            const float e3 = __expf(acc[mi][ni][3]*0.125f);
            *reinterpret_cast<float2*>(&C[(size_t)r0*Sq+c])     = make_float2(e0, e1);
            *reinterpret_cast<float2*>(&C[(size_t)(r0+8)*Sq+c]) = make_float2(e2, e3);
            s0 += e0 + e1;
            s1 += e2 + e3;
        }
        // reduce over the 4 tg lanes sharing row g
        s0 += __shfl_xor_sync(0xffffffffu, s0, 1);
        s0 += __shfl_xor_sync(0xffffffffu, s0, 2);
        s1 += __shfl_xor_sync(0xffffffffu, s1, 1);
        s1 += __shfl_xor_sync(0xffffffffu, s1, 2);
        if (tg == 0){
            psum[wm+mi*16+g][wnidx]   = s0;
            psum[wm+mi*16+g+8][wnidx] = s1;
        }
    }
    __syncthreads();
    if (tid < 128){
        const float t = psum[tid][0] + psum[tid][1] + psum[tid][2] + psum[tid][3];
        g_psum[((size_t)bh*16 + blockIdx.x)*Sq + bm + tid] = t;
    }
}

// ============================================================
// PV + normalize: reads E, normalizes by row sums (from partials),
// writes normalized P back to d_out, computes ctx with normalized P.
// ============================================================
__global__ __launch_bounds__(256,2) void av_kernel(float* __restrict__ scores)
{
    __shared__ char smem[2*16896];
    const int bh = blockIdx.z, b = bh>>4, h = bh&15;
    float* P = scores + (size_t)bh*Sq*Sq;
    const bf16* Vhg = g_vh + (size_t)b*Sq*Dq + h*DHq;
    const bf16* Vlg = g_vl + (size_t)b*Sq*Dq + h*DHq;
    const int tid = threadIdx.x, lane = tid&31, warp = tid>>5;
    const int wm = (warp>>1)*32, wn = (warp&1)*32;
    const int bm = blockIdx.y*128;
    const uint32_t sb = s2u(smem);

    float acc[2][4][4] = {};

    const int va = tid>>7, vr = (tid>>3)&15, vc = tid&7;
    const bf16* vsrc = va ? Vlg : Vhg;
    const int pr = tid>>2, pq = (tid&3)*4;

    // row-sum reconstruction (deterministic)
    float sum0 = 0.f, sum1 = 0.f;
#pragma unroll
    for (int t = 0; t < 16; t++){
        sum0 += g_psum[((size_t)bh*16 + t)*Sq + bm + pr];
        sum1 += g_psum[((size_t)bh*16 + t)*Sq + bm + 64 + pr];
    }
    const float inv0 = 1.0f / sum0;
    const float inv1 = 1.0f / sum1;

    float4 p0, p1, n0, n1;
    p0 = *reinterpret_cast<const float4*>(&P[(size_t)(bm + pr)*Sq + pq]);
    p1 = *reinterpret_cast<const float4*>(&P[(size_t)(bm + 64 + pr)*Sq + pq]);
    {
        uint32_t s = sb + 12288u + (uint32_t)(va*2304 + vr*144 + vc*16);
        cpa16(s, vsrc + (size_t)vr*Dq + vc*8);
        cpcommit();
    }

    for (int kt = 0; kt < 128; kt++){
        const int s = kt&1;
        const uint32_t st = sb + (uint32_t)(s*16896);
        // normalize current tiles, write back to d_out, split into smem
        {
            p0.x *= inv0; p0.y *= inv0; p0.z *= inv0; p0.w *= inv0;
            p1.x *= inv1; p1.y *= inv1; p1.z *= inv1; p1.w *= inv1;
            *reinterpret_cast<float4*>(&P[(size_t)(bm + pr)*Sq + kt*16 + pq])      = p0;
            *reinterpret_cast<float4*>(&P[(size_t)(bm + 64 + pr)*Sq + kt*16 + pq]) = p1;

            bf16 h0,l0,h1,l1,h2,l2,h3,l3;
            char* base = smem + s*16896;
            split2(p0.x,h0,l0); split2(p0.y,h1,l1); split2(p0.z,h2,l2); split2(p0.w,h3,l3);
            *reinterpret_cast<bf162*>(base + pr*48 + pq*2)          = __halves2bfloat162(h0,h1);
            *reinterpret_cast<bf162*>(base + pr*48 + pq*2 + 4)      = __halves2bfloat162(h2,h3);
            *reinterpret_cast<bf162*>(base + 6144 + pr*48 + pq*2)   = __halves2bfloat162(l0,l1);
            *reinterpret_cast<bf162*>(base + 6144 + pr*48 + pq*2+4) = __halves2bfloat162(l2,l3);
            split2(p1.x,h0,l0); split2(p1.y,h1,l1); split2(p1.z,h2,l2); split2(p1.w,h3,l3);
            *reinterpret_cast<bf162*>(base + (pr+64)*48 + pq*2)          = __halves2bfloat162(h0,h1);
            *reinterpret_cast<bf162*>(base + (pr+64)*48 + pq*2 + 4)      = __halves2bfloat162(h2,h3);
            *reinterpret_cast<bf162*>(base + 6144 + (pr+64)*48 + pq*2)   = __halves2bfloat162(l0,l1);
            *reinterpret_cast<bf162*>(base + 6144 + (pr+64)*48 + pq*2+4) = __halves2bfloat162(l2,l3);
        }
        if (kt+1 < 128){
            const int k0 = (kt+1)*16;
            n0 = *reinterpret_cast<const float4*>(&P[(size_t)(bm + pr)*Sq + k0 + pq]);
            n1 = *reinterpret_cast<const float4*>(&P[(size_t)(bm + 64 + pr)*Sq + k0 + pq]);
        }
        cpwait();
        __syncthreads();
        if (kt+1 < 128){
            const int k0 = (kt+1)*16;
            uint32_t sv = sb + (uint32_t)((s^1)*16896) + 12288u + (uint32_t)(va*2304 + vr*144 + vc*16);
            cpa16(sv, vsrc + (size_t)(k0+vr)*Dq + vc*8);
            cpcommit();
        }
        uint32_t bhf[4][2], blf[4][2];
#pragma unroll
        for (int p = 0; p < 2; p++){
            uint32_t addr = st + 12288u +
                (uint32_t)(((lane>>3)&1)*8*144 + (lane&7)*144 + (wn + p*16 + ((lane>>4)&1)*8)*2);
            ldm4t(addr,        bhf[2*p][0], bhf[2*p][1], bhf[2*p+1][0], bhf[2*p+1][1]);
            ldm4t(addr + 2304, blf[2*p][0], blf[2*p][1], blf[2*p+1][0], blf[2*p+1][1]);
        }
#pragma unroll
        for (int mi = 0; mi < 2; mi++){
            uint32_t aaddr = st + (uint32_t)((wm + mi*16 + (lane&15))*48 + ((lane>>4)&1)*16);
            uint32_t a0,a1,a2,a3, l0,l1,l2,l3;
            ldm4(aaddr,        a0,a1,a2,a3);
            ldm4(aaddr + 6144, l0,l1,l2,l3);
#pragma unroll
            for (int ni = 0; ni < 4; ni++){
                mma16(acc[mi][ni], a0,a1,a2,a3, bhf[ni][0], bhf[ni][1]);
                mma16(acc[mi][ni], a0,a1,a2,a3, blf[ni][0], blf[ni][1]);
                mma16(acc[mi][ni], l0,l1,l2,l3, bhf[ni][0], bhf[ni][1]);
            }
        }
        p0 = n0; p1 = n1;
    }

    const int g = lane>>2, tg = lane&3;
#pragma unroll
    for (int mi = 0; mi < 2; mi++)
#pragma unroll
    for (int ni = 0; ni < 4; ni++){
        const int r0 = bm + wm + mi*16 + g;
        const int c  = wn + ni*8 + tg*2;
        const size_t i0 = (size_t)(b*Sq + r0)*Dq + h*DHq + c;
        const size_t i1 = (size_t)(b*Sq + r0 + 8)*Dq + h*DHq + c;
        bf16 h0,l0,h1,l1;
        split2(acc[mi][ni][0],h0,l0); split2(acc[mi][ni][1],h1,l1);
        *reinterpret_cast<bf162*>(&g_ch[i0]) = __halves2bfloat162(h0,h1);
        *reinterpret_cast<bf162*>(&g_cl[i0]) = __halves2bfloat162(l0,l1);
        split2(acc[mi][ni][2],h0,l0); split2(acc[mi][ni][3],h1,l1);
        *reinterpret_cast<bf162*>(&g_ch[i1]) = __halves2bfloat162(h0,h1);
        *reinterpret_cast<bf162*>(&g_cl[i1]) = __halves2bfloat162(l0,l1);
    }
}

// ============================================================
// LayerNorm per row of g_y -> d_out
// ============================================================
__global__ void ln_kernel(const float* __restrict__ gamma,
                          const float* __restrict__ beta,
                          float* __restrict__ out)
{
    const size_t row = blockIdx.x;
    const float4* y = reinterpret_cast<const float4*>(g_y + row * (size_t)Dq);
    float4* o = reinterpret_cast<float4*>(out + row * (size_t)Dq);
    const int tid = threadIdx.x;
    __shared__ float sm[8], sm2[8];

    float4 v = y[tid];
    float s  = v.x + v.y + v.z + v.w;
    float s2 = v.x*v.x + v.y*v.y + v.z*v.z + v.w*v.w;
#pragma unroll
    for (int o2 = 16; o2 > 0; o2 >>= 1) {
        s  += __shfl_xor_sync(0xffffffffu, s,  o2);
        s2 += __shfl_xor_sync(0xffffffffu, s2, o2);
    }
    if ((tid & 31) == 0) { sm[tid>>5] = s; sm2[tid>>5] = s2; }
    __syncthreads();
    float ts = 0.f, ts2 = 0.f;
#pragma unroll
    for (int w = 0; w < 8; w++) { ts += sm[w]; ts2 += sm2[w]; }
    const float mean = ts * (1.0f/Dq);
    const float var  = ts2 * (1.0f/Dq) - mean*mean;
    const float rstd = rsqrtf(var + 1e-6f);

    const float4 gg = reinterpret_cast<const float4*>(gamma)[tid];
    const float4 bb = reinterpret_cast<const float4*>(beta)[tid];
    float4 r;
    r.x = (v.x - mean) * rstd * gg.x + bb.x;
    r.y = (v.y - mean) * rstd * gg.y + bb.y;
    r.z = (v.z - mean) * rstd * gg.z + bb.z;
    r.w = (v.w - mean) * rstd * gg.w + bb.w;
    o[tid] = r;
}

// ============================================================
extern "C" void kernel_launch(void* const* d_in, const int* in_sizes, int n_in,
                              void* d_out, int out_size)
{
    const float* Q     = (const float*)d_in[0];
    const float* K     = (const float*)d_in[1];
    const float* V     = (const float*)d_in[2];
    const float* Wq    = (const float*)d_in[3];
    const float* bq    = (const float*)d_in[4];
    const float* Wk    = (const float*)d_in[5];
    const float* bk    = (const float*)d_in[6];
    const float* Wv    = (const float*)d_in[7];
    const float* bv    = (const float*)d_in[8];
    const float* Wo    = (const float*)d_in[9];
    const float* bo    = (const float*)d_in[10];
    const float* gamma = (const float*)d_in[11];
    const float* beta  = (const float*)d_in[12];

    float* out    = (float*)d_out;
    float* scores = out + OUT_OFF;

    bf16 *wh, *wl, *xh, *xl, *qh, *ql, *kh, *kl, *vh, *vl, *ch, *cl;
    float* gy;
    cudaGetSymbolAddress((void**)&wh, g_wh);
    cudaGetSymbolAddress((void**)&wl, g_wl);
    cudaGetSymbolAddress((void**)&xh, g_xh);
    cudaGetSymbolAddress((void**)&xl, g_xl);
    cudaGetSymbolAddress((void**)&qh, g_qh); cudaGetSymbolAddress((void**)&ql, g_ql);
    cudaGetSymbolAddress((void**)&kh, g_kh); cudaGetSymbolAddress((void**)&kl, g_kl);
    cudaGetSymbolAddress((void**)&vh, g_vh); cudaGetSymbolAddress((void**)&vl, g_vl);
    cudaGetSymbolAddress((void**)&ch, g_ch); cudaGetSymbolAddress((void**)&cl, g_cl);
    cudaGetSymbolAddress((void**)&gy, g_y);

    const int WN = Dq*Dq;

    // prep splits
    split_kernel<<<WN/4/256, 256>>>(Wq, wh + 0*WN, wl + 0*WN, WN/4);
    split_kernel<<<WN/4/256, 256>>>(Wk, wh + 1*WN, wl + 1*WN, WN/4);
    split_kernel<<<WN/4/256, 256>>>(Wv, wh + 2*WN, wl + 2*WN, WN/4);
    split_kernel<<<WN/4/256, 256>>>(Wo, wh + 3*WN, wl + 3*WN, WN/4);
    split_kernel<<<NELEM/4/256, 256>>>(Q, xh + 0*(size_t)NELEM, xl + 0*(size_t)NELEM, NELEM/4);
    split_kernel<<<NELEM/4/256, 256>>>(K, xh + 1*(size_t)NELEM, xl + 1*(size_t)NELEM, NELEM/4);
    split_kernel<<<NELEM/4/256, 256>>>(V, xh + 2*(size_t)NELEM, xl + 2*(size_t)NELEM, NELEM/4);

    dim3 blk(256);
    dim3 gProj(Dq/128, Mq/128);
    proj_kernel<<<gProj, blk>>>(xh+0*(size_t)NELEM, xl+0*(size_t)NELEM, wh+0*WN, wl+0*WN,
                                bq, nullptr, qh, ql, nullptr);
    proj_kernel<<<gProj, blk>>>(xh+1*(size_t)NELEM, xl+1*(size_t)NELEM, wh+1*WN, wl+1*WN,
                                bk, nullptr, kh, kl, nullptr);
    proj_kernel<<<gProj, blk>>>(xh+2*(size_t)NELEM, xl+2*(size_t)NELEM, wh+2*WN, wl+2*WN,
                                bv, nullptr, vh, vl, nullptr);

    // scores -> E = exp(S/8) + partial row sums (no separate softmax pass)
    dim3 gSc(Sq/128, Sq/128, Bq*Hq);   // (16,16,32)
    scores_kernel<<<gSc, blk>>>(scores);

    // PV + normalization + normalized-P writeback
    dim3 gAv(1, Sq/128, Bq*Hq);        // (1,16,32)
    av_kernel<<<gAv, blk>>>(scores);

    proj_kernel<<<gProj, blk>>>(ch, cl, wh+3*WN, wl+3*WN, bo, Q, nullptr, nullptr, gy);

    ln_kernel<<<(unsigned)Mq, blk>>>(gamma, beta, out);
}

// round 8
// speedup vs baseline: 1.3587x; 1.1316x over previous
#include <cuda_runtime.h>
#include <cuda_bf16.h>
#include <math.h>
#include <stdint.h>

#define Bq 2
#define Sq 2048
#define Dq 1024
#define Hq 16
#define DHq 64
#define Mq (Bq*Sq)
#define NELEM (Mq*Dq)
#define WN (Dq*Dq)
#define OUT_OFF ((size_t)Mq*Dq)

typedef __nv_bfloat16 bf16;
typedef __nv_bfloat162 bf162;

// SW128 swizzle (byte offsets)
#define SWZ(x) ((x) ^ ((((uint32_t)(x))>>3)&0x70))

// ---------------- global scratch (no allocs allowed) ----------------
// tile-major pre-swizzled (SW128) operands: 128-row x 64-col bf16 tiles (16KB),
// tile index = (row>>7)*16 + (col>>6)
__device__ __align__(16) bf16 g_pah[3][NELEM], g_pal[3][NELEM];   // inputs Q,K,V
__device__ __align__(16) bf16 g_pwh[4][WN],    g_pwl[4][WN];      // weights
__device__ __align__(16) bf16 g_pch[NELEM],    g_pcl[NELEM];      // ctx
// row-major split outputs of q/k/v projections (consumed by scores/av)
__device__ __align__(16) bf16 g_qh[NELEM], g_ql[NELEM];
__device__ __align__(16) bf16 g_kh[NELEM], g_kl[NELEM];
__device__ __align__(16) bf16 g_vh[NELEM], g_vl[NELEM];
__device__ float g_y[NELEM];
__device__ float g_psum[(size_t)Bq*Hq*16*Sq];

// ---------------- helpers ----------------
__device__ __forceinline__ uint32_t s2u(const void* p){ return (uint32_t)__cvta_generic_to_shared(p); }
__device__ __forceinline__ void cpa16(uint32_t s, const void* g){
    asm volatile("cp.async.cg.shared.global [%0], [%1], 16;\n" :: "r"(s), "l"(g));
}
__device__ __forceinline__ void cpcommit(){ asm volatile("cp.async.commit_group;\n" ::: "memory"); }
__device__ __forceinline__ void cpwait(){ asm volatile("cp.async.wait_group 0;\n" ::: "memory"); }
__device__ __forceinline__ void ldm4(uint32_t a, uint32_t&r0,uint32_t&r1,uint32_t&r2,uint32_t&r3){
    asm volatile("ldmatrix.sync.aligned.m8n8.x4.shared.b16 {%0,%1,%2,%3}, [%4];\n"
        : "=r"(r0),"=r"(r1),"=r"(r2),"=r"(r3) : "r"(a));
}
__device__ __forceinline__ void ldm4t(uint32_t a, uint32_t&r0,uint32_t&r1,uint32_t&r2,uint32_t&r3){
    asm volatile("ldmatrix.sync.aligned.m8n8.x4.trans.shared.b16 {%0,%1,%2,%3}, [%4];\n"
        : "=r"(r0),"=r"(r1),"=r"(r2),"=r"(r3) : "r"(a));
}
__device__ __forceinline__ void mma16(float* c, uint32_t a0,uint32_t a1,uint32_t a2,uint32_t a3,
                                      uint32_t b0,uint32_t b1){
    asm volatile("mma.sync.aligned.m16n8k16.row.col.f32.bf16.bf16.f32 "
        "{%0,%1,%2,%3}, {%4,%5,%6,%7}, {%8,%9}, {%0,%1,%2,%3};\n"
        : "+f"(c[0]),"+f"(c[1]),"+f"(c[2]),"+f"(c[3])
        : "r"(a0),"r"(a1),"r"(a2),"r"(a3),"r"(b0),"r"(b1));
}
__device__ __forceinline__ void split2(float x, bf16& h, bf16& l){
    h = __float2bfloat16(x);
    l = __float2bfloat16(x - __bfloat162float(h));
}

// ---- bulk TMA + mbarrier (plain sm_90 PTX — compiles for compute_103) ----
__device__ __forceinline__ void bulk_ld(uint32_t dst, const void* src, uint32_t bytes, uint32_t mbar){
    asm volatile("cp.async.bulk.shared::cta.global.mbarrier::complete_tx::bytes [%0], [%1], %2, [%3];\n"
        :: "r"(dst), "l"(src), "r"(bytes), "r"(mbar) : "memory");
}
__device__ __forceinline__ void mbar_init(uint32_t mbar, uint32_t cnt){
    asm volatile("mbarrier.init.shared.b64 [%0], %1;\n" :: "r"(mbar), "r"(cnt) : "memory");
}
__device__ __forceinline__ void mbar_expect(uint32_t mbar, uint32_t tx){
    asm volatile("mbarrier.arrive.expect_tx.shared.b64 _, [%0], %1;\n" :: "r"(mbar), "r"(tx) : "memory");
}
__device__ __forceinline__ void mbar_wait(uint32_t mbar, uint32_t parity){
    asm volatile("{\n\t.reg .pred P;\n\t"
        "W%=:\n\t"
        "mbarrier.try_wait.parity.acquire.cta.shared::cta.b64 P, [%0], %1, 0x989680;\n\t"
        "@!P bra W%=;\n\t}\n"
        :: "r"(mbar), "r"(parity) : "memory");
}

// ---------------- split f32 -> tile-major pre-swizzled bf16 hi/lo ----------------
// works for any [R x 1024] f32 matrix (inputs and weights share the formula)
__global__ void split_tile(const float* __restrict__ x, bf16* __restrict__ th,
                           bf16* __restrict__ tl, int n4)
{
    int i = blockIdx.x*blockDim.x + threadIdx.x;
    if (i >= n4) return;
    const int r = i >> 8, c4 = (i & 255) << 2;
    float4 v = reinterpret_cast<const float4*>(x)[i];
    bf16 h0,l0,h1,l1,h2,l2,h3,l3;
    split2(v.x,h0,l0); split2(v.y,h1,l1); split2(v.z,h2,l2); split2(v.w,h3,l3);
    const size_t tile = (size_t)((r>>7)*16 + (c4>>6)) * 16384;  // bytes
    const uint32_t off = SWZ(((r&127)<<7) + ((c4&63)<<1));
    char* dh = (char*)th + tile + off;
    char* dl = (char*)tl + tile + off;
    *reinterpret_cast<bf162*>(dh)   = __halves2bfloat162(h0,h1);
    *reinterpret_cast<bf162*>(dh+4) = __halves2bfloat162(h2,h3);
    *reinterpret_cast<bf162*>(dl)   = __halves2bfloat162(l0,l1);
    *reinterpret_cast<bf162*>(dl+4) = __halves2bfloat162(l2,l3);
}

// ============================================================
// Projection GEMM (NT, mma.sync, bulk-TMA staged): C[128,128] tile,
// BK=64, 2 stages x 64KB, 8 warps (64x32 warp tiles), bf16x3 split.
// ============================================================
#define PR_STAGE 65536
#define PR_SMEM  (128 + 2*PR_STAGE)

__global__ __launch_bounds__(256,1) void proj_kernel(
    const bf16* __restrict__ Ahg, const bf16* __restrict__ Alg,
    const bf16* __restrict__ Bhg, const bf16* __restrict__ Blg,
    const float* __restrict__ bias, const float* __restrict__ resid,
    bf16* __restrict__ outh, bf16* __restrict__ outl, float* __restrict__ outf)
{
    extern __shared__ __align__(128) char sm_[];
    const int tid = threadIdx.x, lane = tid&31, warp = tid>>5;
    const int n0 = blockIdx.x, m0 = blockIdx.y;
    const uint32_t sb = s2u(sm_);
    const uint32_t dat = sb + 128;

    if (tid == 0){
        mbar_init(sb+0, 1);
        mbar_init(sb+8, 1);
#pragma unroll
        for (int p = 0; p < 2; p++){
            const uint32_t mb = sb + p*8;
            const uint32_t buf = dat + p*PR_STAGE;
            mbar_expect(mb, PR_STAGE);
            bulk_ld(buf,        (const char*)Ahg + (size_t)(m0*16+p)*16384, 16384, mb);
            bulk_ld(buf+16384,  (const char*)Alg + (size_t)(m0*16+p)*16384, 16384, mb);
            bulk_ld(buf+32768,  (const char*)Bhg + (size_t)(n0*16+p)*16384, 16384, mb);
            bulk_ld(buf+49152,  (const char*)Blg + (size_t)(n0*16+p)*16384, 16384, mb);
        }
    }
    __syncthreads();

    const int wm = (warp>>2)*64, wn = (warp&3)*32;
    float acc[4][4][4] = {};

    for (int kt = 0; kt < 16; kt++){
        const int b = kt & 1;
        mbar_wait(sb + b*8, (kt>>1)&1);
        const uint32_t buf = dat + b*PR_STAGE;
#pragma unroll
        for (int ks = 0; ks < 4; ks++){
            uint32_t bhf[4][2], blf[4][2];
#pragma unroll
            for (int p = 0; p < 2; p++){
                const uint32_t roff = (uint32_t)(wn + p*16 + (lane&7) + ((lane>>4)&1)*8)*128
                                      + ks*32 + ((lane>>3)&1)*16;
                ldm4(buf + 32768 + SWZ(roff), bhf[2*p][0], bhf[2*p][1], bhf[2*p+1][0], bhf[2*p+1][1]);
                ldm4(buf + 49152 + SWZ(roff), blf[2*p][0], blf[2*p][1], blf[2*p+1][0], blf[2*p+1][1]);
            }
#pragma unroll
            for (int mi = 0; mi < 4; mi++){
                const uint32_t roff = (uint32_t)(wm + mi*16 + (lane&15))*128
                                      + ks*32 + ((lane>>4)&1)*16;
                uint32_t a0,a1,a2,a3, l0,l1,l2,l3;
                ldm4(buf +         SWZ(roff), a0,a1,a2,a3);
                ldm4(buf + 16384 + SWZ(roff), l0,l1,l2,l3);
#pragma unroll
                for (int ni = 0; ni < 4; ni++){
                    mma16(acc[mi][ni], a0,a1,a2,a3, bhf[ni][0], bhf[ni][1]);
                    mma16(acc[mi][ni], a0,a1,a2,a3, blf[ni][0], blf[ni][1]);
                    mma16(acc[mi][ni], l0,l1,l2,l3, bhf[ni][0], bhf[ni][1]);
                }
            }
        }
        __syncthreads();   // all warps done with buffer b
        if (tid == 0 && kt+2 < 16){
            const uint32_t mb = sb + b*8;
            mbar_expect(mb, PR_STAGE);
            bulk_ld(buf,        (const char*)Ahg + (size_t)(m0*16+kt+2)*16384, 16384, mb);
            bulk_ld(buf+16384,  (const char*)Alg + (size_t)(m0*16+kt+2)*16384, 16384, mb);
            bulk_ld(buf+32768,  (const char*)Bhg + (size_t)(n0*16+kt+2)*16384, 16384, mb);
            bulk_ld(buf+49152,  (const char*)Blg + (size_t)(n0*16+kt+2)*16384, 16384, mb);
        }
    }

    // epilogue
    const int bm = m0*128, bn = n0*128;
    const int g = lane>>2, tg = lane&3;
#pragma unroll
    for (int mi=0; mi<4; mi++)
#pragma unroll
    for (int ni=0; ni<4; ni++){
        const int r0 = bm+wm+mi*16+g;
        const int c  = bn+wn+ni*8+tg*2;
        const float2 bv = *reinterpret_cast<const float2*>(&bias[c]);
        const float x0=acc[mi][ni][0]+bv.x, x1=acc[mi][ni][1]+bv.y;
        const float x2=acc[mi][ni][2]+bv.x, x3=acc[mi][ni][3]+bv.y;
        if (outf){
            const float2 q0 = *reinterpret_cast<const float2*>(&resid[(size_t)r0*Dq + c]);
            const float2 q1 = *reinterpret_cast<const float2*>(&resid[(size_t)(r0+8)*Dq + c]);
            *reinterpret_cast<float2*>(&outf[(size_t)r0*Dq+c])     = make_float2(x0+q0.x, x1+q0.y);
            *reinterpret_cast<float2*>(&outf[(size_t)(r0+8)*Dq+c]) = make_float2(x2+q1.x, x3+q1.y);
        } else {
            bf16 h0,l0,h1,l1;
            split2(x0,h0,l0); split2(x1,h1,l1);
            *reinterpret_cast<bf162*>(&outh[(size_t)r0*Dq+c]) = __halves2bfloat162(h0,h1);
            *reinterpret_cast<bf162*>(&outl[(size_t)r0*Dq+c]) = __halves2bfloat162(l0,l1);
            split2(x2,h0,l0); split2(x3,h1,l1);
            *reinterpret_cast<bf162*>(&outh[(size_t)(r0+8)*Dq+c]) = __halves2bfloat162(h0,h1);
            *reinterpret_cast<bf162*>(&outl[(size_t)(r0+8)*Dq+c]) = __halves2bfloat162(l0,l1);
        }
    }
}

// ============================================================
// mma.sync GEMM core for scores (unchanged, known-good)
// ============================================================
template<int KT>
__device__ __forceinline__ void gemm_core(
    const bf16* __restrict__ Ahg, const bf16* __restrict__ Alg,
    const bf16* __restrict__ Bhg, const bf16* __restrict__ Blg,
    int bm, int bn, char* smem, float acc[4][4][4])
{
    const int tid = threadIdx.x;
    const int lane = tid & 31, warp = tid >> 5;
    const int wm = (warp>>2)*64, wn = (warp&3)*32;
    const uint32_t sb = s2u(smem);
    const int row = tid>>1, hf = tid&1;

    {
        uint32_t s0 = sb + (uint32_t)(row*48 + hf*16);
        size_t ga = (size_t)(bm+row)*Dq + hf*8;
        size_t gb = (size_t)(bn+row)*Dq + hf*8;
        cpa16(s0 + 0,     Ahg + ga);
        cpa16(s0 + 6144,  Alg + ga);
        cpa16(s0 + 12288, Bhg + gb);
        cpa16(s0 + 18432, Blg + gb);
        cpcommit();
    }

    for (int kt = 0; kt < KT; kt++){
        cpwait();
        __syncthreads();
        if (kt+1 < KT){
            uint32_t s0 = sb + (uint32_t)(((kt+1)&1)*24576 + row*48 + hf*16);
            const int k0 = (kt+1)*16;
            size_t ga = (size_t)(bm+row)*Dq + k0 + hf*8;
            size_t gb = (size_t)(bn+row)*Dq + k0 + hf*8;
            cpa16(s0 + 0,     Ahg + ga);
            cpa16(s0 + 6144,  Alg + ga);
            cpa16(s0 + 12288, Bhg + gb);
            cpa16(s0 + 18432, Blg + gb);
            cpcommit();
        }
        const uint32_t st = sb + (uint32_t)((kt&1)*24576);
        uint32_t bhf[4][2], blf[4][2];
#pragma unroll
        for (int p = 0; p < 2; p++){
            uint32_t addr = st + 12288u +
                (uint32_t)((wn + p*16 + (lane&7) + ((lane>>4)&1)*8)*48 + ((lane>>3)&1)*16);
            ldm4(addr,        bhf[2*p][0], bhf[2*p][1], bhf[2*p+1][0], bhf[2*p+1][1]);
            ldm4(addr + 6144, blf[2*p][0], blf[2*p][1], blf[2*p+1][0], blf[2*p+1][1]);
        }
#pragma unroll
        for (int mi = 0; mi < 4; mi++){
            uint32_t aaddr = st + (uint32_t)((wm + mi*16 + (lane&15))*48 + ((lane>>4)&1)*16);
            uint32_t a0,a1,a2,a3, l0,l1,l2,l3;
            ldm4(aaddr,        a0,a1,a2,a3);
            ldm4(aaddr + 6144, l0,l1,l2,l3);
#pragma unroll
            for (int ni = 0; ni < 4; ni++){
                mma16(acc[mi][ni], a0,a1,a2,a3, bhf[ni][0], bhf[ni][1]);
                mma16(acc[mi][ni], a0,a1,a2,a3, blf[ni][0], blf[ni][1]);
                mma16(acc[mi][ni], l0,l1,l2,l3, bhf[ni][0], bhf[ni][1]);
            }
        }
    }
}

// ============================================================
// Scores: per (b,h) E[q,k] = exp((q.k)/8) + partial row sums
// ============================================================
__global__ __launch_bounds__(256,2) void scores_kernel(float* __restrict__ scores)
{
    __shared__ char smem[49152];
    const int bh = blockIdx.z, b = bh>>4, h = bh&15;
    const size_t boff = (size_t)b*Sq*Dq + h*DHq;
    float acc[4][4][4] = {};
    const int bm = blockIdx.y*128, bn = blockIdx.x*128;
    gemm_core<4>(g_qh+boff, g_ql+boff, g_kh+boff, g_kl+boff, bm, bn, smem, acc);

    __shared__ float psum[128][4];

    float* C = scores + (size_t)bh*Sq*Sq;
    const int tid = threadIdx.x;
    const int lane = tid & 31, warp = tid>>5;
    const int wm=(warp>>2)*64, wn=(warp&3)*32, g=lane>>2, tg=lane&3;
    const int wnidx = warp & 3;
#pragma unroll
    for (int mi=0; mi<4; mi++){
        float s0 = 0.f, s1 = 0.f;
#pragma unroll
        for (int ni=0; ni<4; ni++){
            const int r0 = bm+wm+mi*16+g;
            const int c  = bn+wn+ni*8+tg*2;
            const float e0 = __expf(acc[mi][ni][0]*0.125f);
            const float e1 = __expf(acc[mi][ni][1]*0.125f);
            const float e2 = __expf(acc[mi][ni][2]*0.125f);
            const float e3 = __expf(acc[mi][ni][3]*0.125f);
            *reinterpret_cast<float2*>(&C[(size_t)r0*Sq+c])     = make_float2(e0, e1);
            *reinterpret_cast<float2*>(&C[(size_t)(r0+8)*Sq+c]) = make_float2(e2, e3);
            s0 += e0 + e1;
            s1 += e2 + e3;
        }
        s0 += __shfl_xor_sync(0xffffffffu, s0, 1);
        s0 += __shfl_xor_sync(0xffffffffu, s0, 2);
        s1 += __shfl_xor_sync(0xffffffffu, s1, 1);
        s1 += __shfl_xor_sync(0xffffffffu, s1, 2);
        if (tg == 0){
            psum[wm+mi*16+g][wnidx]   = s0;
            psum[wm+mi*16+g+8][wnidx] = s1;
        }
    }
    __syncthreads();
    if (tid < 128){
        const float t = psum[tid][0] + psum[tid][1] + psum[tid][2] + psum[tid][3];
        g_psum[((size_t)bh*16 + blockIdx.x)*Sq + bm + tid] = t;
    }
}

// ============================================================
// PV + normalize; ctx written tile-major swizzled for the O projection
// ============================================================
__global__ __launch_bounds__(256,2) void av_kernel(float* __restrict__ scores)
{
    __shared__ char smem[2*16896];
    const int bh = blockIdx.z, b = bh>>4, h = bh&15;
    float* P = scores + (size_t)bh*Sq*Sq;
    const bf16* Vhg = g_vh + (size_t)b*Sq*Dq + h*DHq;
    const bf16* Vlg = g_vl + (size_t)b*Sq*Dq + h*DHq;
    const int tid = threadIdx.x, lane = tid&31, warp = tid>>5;
    const int wm = (warp>>1)*32, wn = (warp&1)*32;
    const int bm = blockIdx.y*128;
    const uint32_t sb = s2u(smem);

    float acc[2][4][4] = {};

    const int va = tid>>7, vr = (tid>>3)&15, vc = tid&7;
    const bf16* vsrc = va ? Vlg : Vhg;
    const int pr = tid>>2, pq = (tid&3)*4;

    float sum0 = 0.f, sum1 = 0.f;
#pragma unroll
    for (int t = 0; t < 16; t++){
        sum0 += g_psum[((size_t)bh*16 + t)*Sq + bm + pr];
        sum1 += g_psum[((size_t)bh*16 + t)*Sq + bm + 64 + pr];
    }
    const float inv0 = 1.0f / sum0;
    const float inv1 = 1.0f / sum1;

    float4 p0, p1, n0, n1;
    p0 = *reinterpret_cast<const float4*>(&P[(size_t)(bm + pr)*Sq + pq]);
    p1 = *reinterpret_cast<const float4*>(&P[(size_t)(bm + 64 + pr)*Sq + pq]);
    {
        uint32_t s = sb + 12288u + (uint32_t)(va*2304 + vr*144 + vc*16);
        cpa16(s, vsrc + (size_t)vr*Dq + vc*8);
        cpcommit();
    }

    for (int kt = 0; kt < 128; kt++){
        const int s = kt&1;
        const uint32_t st = sb + (uint32_t)(s*16896);
        {
            p0.x *= inv0; p0.y *= inv0; p0.z *= inv0; p0.w *= inv0;
            p1.x *= inv1; p1.y *= inv1; p1.z *= inv1; p1.w *= inv1;
            *reinterpret_cast<float4*>(&P[(size_t)(bm + pr)*Sq + kt*16 + pq])      = p0;
            *reinterpret_cast<float4*>(&P[(size_t)(bm + 64 + pr)*Sq + kt*16 + pq]) = p1;

            bf16 h0,l0,h1,l1,h2,l2,h3,l3;
            char* base = smem + s*16896;
            split2(p0.x,h0,l0); split2(p0.y,h1,l1); split2(p0.z,h2,l2); split2(p0.w,h3,l3);
            *reinterpret_cast<bf162*>(base + pr*48 + pq*2)          = __halves2bfloat162(h0,h1);
            *reinterpret_cast<bf162*>(base + pr*48 + pq*2 + 4)      = __halves2bfloat162(h2,h3);
            *reinterpret_cast<bf162*>(base + 6144 + pr*48 + pq*2)   = __halves2bfloat162(l0,l1);
            *reinterpret_cast<bf162*>(base + 6144 + pr*48 + pq*2+4) = __halves2bfloat162(l2,l3);
            split2(p1.x,h0,l0); split2(p1.y,h1,l1); split2(p1.z,h2,l2); split2(p1.w,h3,l3);
            *reinterpret_cast<bf162*>(base + (pr+64)*48 + pq*2)          = __halves2bfloat162(h0,h1);
            *reinterpret_cast<bf162*>(base + (pr+64)*48 + pq*2 + 4)      = __halves2bfloat162(h2,h3);
            *reinterpret_cast<bf162*>(base + 6144 + (pr+64)*48 + pq*2)   = __halves2bfloat162(l0,l1);
            *reinterpret_cast<bf162*>(base + 6144 + (pr+64)*48 + pq*2+4) = __halves2bfloat162(l2,l3);
        }
        if (kt+1 < 128){
            const int k0 = (kt+1)*16;
            n0 = *reinterpret_cast<const float4*>(&P[(size_t)(bm + pr)*Sq + k0 + pq]);
            n1 = *reinterpret_cast<const float4*>(&P[(size_t)(bm + 64 + pr)*Sq + k0 + pq]);
        }
        cpwait();
        __syncthreads();
        if (kt+1 < 128){
            const int k0 = (kt+1)*16;
            uint32_t sv = sb + (uint32_t)((s^1)*16896) + 12288u + (uint32_t)(va*2304 + vr*144 + vc*16);
            cpa16(sv, vsrc + (size_t)(k0+vr)*Dq + vc*8);
            cpcommit();
        }
        uint32_t bhf[4][2], blf[4][2];
#pragma unroll
        for (int p = 0; p < 2; p++){
            uint32_t addr = st + 12288u +
                (uint32_t)(((lane>>3)&1)*8*144 + (lane&7)*144 + (wn + p*16 + ((lane>>4)&1)*8)*2);
            ldm4t(addr,        bhf[2*p][0], bhf[2*p][1], bhf[2*p+1][0], bhf[2*p+1][1]);
            ldm4t(addr + 2304, blf[2*p][0], blf[2*p][1], blf[2*p+1][0], blf[2*p+1][1]);
        }
#pragma unroll
        for (int mi = 0; mi < 2; mi++){
            uint32_t aaddr = st + (uint32_t)((wm + mi*16 + (lane&15))*48 + ((lane>>4)&1)*16);
            uint32_t a0,a1,a2,a3, l0,l1,l2,l3;
            ldm4(aaddr,        a0,a1,a2,a3);
            ldm4(aaddr + 6144, l0,l1,l2,l3);
#pragma unroll
            for (int ni = 0; ni < 4; ni++){
                mma16(acc[mi][ni], a0,a1,a2,a3, bhf[ni][0], bhf[ni][1]);
                mma16(acc[mi][ni], a0,a1,a2,a3, blf[ni][0], blf[ni][1]);
                mma16(acc[mi][ni], l0,l1,l2,l3, bhf[ni][0], bhf[ni][1]);
            }
        }
        p0 = n0; p1 = n1;
    }

    // epilogue: ctx -> tile-major pre-swizzled layout (tile col index == head)
    const int g = lane>>2, tg = lane&3;
#pragma unroll
    for (int mi = 0; mi < 2; mi++)
#pragma unroll
    for (int ni = 0; ni < 4; ni++){
        const int r0 = bm + wm + mi*16 + g;
        const int c  = wn + ni*8 + tg*2;
#pragma unroll
        for (int hh = 0; hh < 2; hh++){
            const int grow = b*Sq + r0 + hh*8;
            const size_t tb = ((size_t)((grow>>7)*16 + h)) * 16384;   // bytes
            const uint32_t off = SWZ(((grow&127)<<7) + (c<<1));
            const float x0 = acc[mi][ni][hh*2+0];
            const float x1 = acc[mi][ni][hh*2+1];
            bf16 h0,l0,h1,l1;
            split2(x0,h0,l0); split2(x1,h1,l1);
            *reinterpret_cast<bf162*>((char*)g_pch + tb + off) = __halves2bfloat162(h0,h1);
            *reinterpret_cast<bf162*>((char*)g_pcl + tb + off) = __halves2bfloat162(l0,l1);
        }
    }
}

// ============================================================
// LayerNorm per row of g_y -> d_out
// ============================================================
__global__ void ln_kernel(const float* __restrict__ gamma,
                          const float* __restrict__ beta,
                          float* __restrict__ out)
{
    const size_t row = blockIdx.x;
    const float4* y = reinterpret_cast<const float4*>(g_y + row * (size_t)Dq);
    float4* o = reinterpret_cast<float4*>(out + row * (size_t)Dq);
    const int tid = threadIdx.x;
    __shared__ float sm[8], sm2[8];

    float4 v = y[tid];
    float s  = v.x + v.y + v.z + v.w;
    float s2 = v.x*v.x + v.y*v.y + v.z*v.z + v.w*v.w;
#pragma unroll
    for (int o2 = 16; o2 > 0; o2 >>= 1) {
        s  += __shfl_xor_sync(0xffffffffu, s,  o2);
        s2 += __shfl_xor_sync(0xffffffffu, s2, o2);
    }
    if ((tid & 31) == 0) { sm[tid>>5] = s; sm2[tid>>5] = s2; }
    __syncthreads();
    float ts = 0.f, ts2 = 0.f;
#pragma unroll
    for (int w = 0; w < 8; w++) { ts += sm[w]; ts2 += sm2[w]; }
    const float mean = ts * (1.0f/Dq);
    const float var  = ts2 * (1.0f/Dq) - mean*mean;
    const float rstd = rsqrtf(var + 1e-6f);

    const float4 gg = reinterpret_cast<const float4*>(gamma)[tid];
    const float4 bb = reinterpret_cast<const float4*>(beta)[tid];
    float4 r;
    r.x = (v.x - mean) * rstd * gg.x + bb.x;
    r.y = (v.y - mean) * rstd * gg.y + bb.y;
    r.z = (v.z - mean) * rstd * gg.z + bb.z;
    r.w = (v.w - mean) * rstd * gg.w + bb.w;
    o[tid] = r;
}

// ============================================================
extern "C" void kernel_launch(void* const* d_in, const int* in_sizes, int n_in,
                              void* d_out, int out_size)
{
    const float* Q     = (const float*)d_in[0];
    const float* K     = (const float*)d_in[1];
    const float* V     = (const float*)d_in[2];
    const float* Wq    = (const float*)d_in[3];
    const float* bq    = (const float*)d_in[4];
    const float* Wk    = (const float*)d_in[5];
    const float* bk    = (const float*)d_in[6];
    const float* Wv    = (const float*)d_in[7];
    const float* bv    = (const float*)d_in[8];
    const float* Wo    = (const float*)d_in[9];
    const float* bo    = (const float*)d_in[10];
    const float* gamma = (const float*)d_in[11];
    const float* beta  = (const float*)d_in[12];

    float* out    = (float*)d_out;
    float* scores = out + OUT_OFF;

    bf16 *pah, *pal, *pwh, *pwl, *pch, *pcl;
    bf16 *qh, *ql, *kh, *kl, *vh, *vl;
    float* gy;
    cudaGetSymbolAddress((void**)&pah, g_pah);
    cudaGetSymbolAddress((void**)&pal, g_pal);
    cudaGetSymbolAddress((void**)&pwh, g_pwh);
    cudaGetSymbolAddress((void**)&pwl, g_pwl);
    cudaGetSymbolAddress((void**)&pch, g_pch);
    cudaGetSymbolAddress((void**)&pcl, g_pcl);
    cudaGetSymbolAddress((void**)&qh, g_qh); cudaGetSymbolAddress((void**)&ql, g_ql);
    cudaGetSymbolAddress((void**)&kh, g_kh); cudaGetSymbolAddress((void**)&kl, g_kl);
    cudaGetSymbolAddress((void**)&vh, g_vh); cudaGetSymbolAddress((void**)&vl, g_vl);
    cudaGetSymbolAddress((void**)&gy, g_y);

    static bool attr_set = false;
    if (!attr_set){
        cudaFuncSetAttribute(proj_kernel, cudaFuncAttributeMaxDynamicSharedMemorySize, PR_SMEM);
        attr_set = true;
    }

    dim3 blk(256);

    // splits into tile-major pre-swizzled layouts (inputs + weights, same formula)
    split_tile<<<NELEM/4/256, 256>>>(Q, pah + 0*(size_t)NELEM, pal + 0*(size_t)NELEM, NELEM/4);
    split_tile<<<NELEM/4/256, 256>>>(K, pah + 1*(size_t)NELEM, pal + 1*(size_t)NELEM, NELEM/4);
    split_tile<<<NELEM/4/256, 256>>>(V, pah + 2*(size_t)NELEM, pal + 2*(size_t)NELEM, NELEM/4);
    split_tile<<<WN/4/256, 256>>>(Wq, pwh + 0*(size_t)WN, pwl + 0*(size_t)WN, WN/4);
    split_tile<<<WN/4/256, 256>>>(Wk, pwh + 1*(size_t)WN, pwl + 1*(size_t)WN, WN/4);
    split_tile<<<WN/4/256, 256>>>(Wv, pwh + 2*(size_t)WN, pwl + 2*(size_t)WN, WN/4);
    split_tile<<<WN/4/256, 256>>>(Wo, pwh + 3*(size_t)WN, pwl + 3*(size_t)WN, WN/4);

    // projections (mma.sync + bulk-TMA staging)
    dim3 gP(8, 32);
    proj_kernel<<<gP, blk, PR_SMEM>>>(pah+0*(size_t)NELEM, pal+0*(size_t)NELEM,
                                      pwh+0*(size_t)WN, pwl+0*(size_t)WN,
                                      bq, nullptr, qh, ql, nullptr);
    proj_kernel<<<gP, blk, PR_SMEM>>>(pah+1*(size_t)NELEM, pal+1*(size_t)NELEM,
                                      pwh+1*(size_t)WN, pwl+1*(size_t)WN,
                                      bk, nullptr, kh, kl, nullptr);
    proj_kernel<<<gP, blk, PR_SMEM>>>(pah+2*(size_t)NELEM, pal+2*(size_t)NELEM,
                                      pwh+2*(size_t)WN, pwl+2*(size_t)WN,
                                      bv, nullptr, vh, vl, nullptr);

    // scores -> E = exp(S/8) + partial row sums
    dim3 gSc(Sq/128, Sq/128, Bq*Hq);
    scores_kernel<<<gSc, blk>>>(scores);

    // PV + normalization + normalized-P writeback; ctx -> tile-major
    dim3 gAv(1, Sq/128, Bq*Hq);
    av_kernel<<<gAv, blk>>>(scores);

    // O projection + bias + residual -> g_y
    proj_kernel<<<gP, blk, PR_SMEM>>>(pch, pcl, pwh+3*(size_t)WN, pwl+3*(size_t)WN,
                                      bo, Q, nullptr, nullptr, gy);

    ln_kernel<<<(unsigned)Mq, blk>>>(gamma, beta, out);
}

// round 9
// speedup vs baseline: 1.4630x; 1.0768x over previous
#include <cuda_runtime.h>
#include <cuda_bf16.h>
#include <math.h>
#include <stdint.h>

#define Bq 2
#define Sq 2048
#define Dq 1024
#define Hq 16
#define DHq 64
#define Mq (Bq*Sq)
#define NELEM (Mq*Dq)
#define WN (Dq*Dq)
#define OUT_OFF ((size_t)Mq*Dq)

typedef __nv_bfloat16 bf16;
typedef __nv_bfloat162 bf162;

// SW128 swizzle (byte offsets)
#define SWZ(x) ((x) ^ ((((uint32_t)(x))>>3)&0x70))

// ---------------- global scratch (no allocs allowed) ----------------
// tile-major pre-swizzled (SW128): 128-row x 64-col bf16 tiles (16KB),
// tile index = (row>>7)*16 + (col>>6)
__device__ __align__(16) bf16 g_pah[3][NELEM], g_pal[3][NELEM];   // inputs Q,K,V
__device__ __align__(16) bf16 g_pwh[4][WN],    g_pwl[4][WN];      // weights
__device__ __align__(16) bf16 g_pch[NELEM],    g_pcl[NELEM];      // ctx
// q/k: TILE-MAJOR swizzled (consumed by scores via bulk-TMA)
__device__ __align__(16) bf16 g_qh[NELEM], g_ql[NELEM];
__device__ __align__(16) bf16 g_kh[NELEM], g_kl[NELEM];
// v: row-major split (consumed by av)
__device__ __align__(16) bf16 g_vh[NELEM], g_vl[NELEM];
__device__ float g_y[NELEM];
__device__ float g_psum[(size_t)Bq*Hq*16*Sq];

// ---------------- helpers ----------------
__device__ __forceinline__ uint32_t s2u(const void* p){ return (uint32_t)__cvta_generic_to_shared(p); }
__device__ __forceinline__ void cpa16(uint32_t s, const void* g){
    asm volatile("cp.async.cg.shared.global [%0], [%1], 16;\n" :: "r"(s), "l"(g));
}
__device__ __forceinline__ void cpcommit(){ asm volatile("cp.async.commit_group;\n" ::: "memory"); }
__device__ __forceinline__ void cpwait(){ asm volatile("cp.async.wait_group 0;\n" ::: "memory"); }
__device__ __forceinline__ void ldm4(uint32_t a, uint32_t&r0,uint32_t&r1,uint32_t&r2,uint32_t&r3){
    asm volatile("ldmatrix.sync.aligned.m8n8.x4.shared.b16 {%0,%1,%2,%3}, [%4];\n"
        : "=r"(r0),"=r"(r1),"=r"(r2),"=r"(r3) : "r"(a));
}
__device__ __forceinline__ void ldm4t(uint32_t a, uint32_t&r0,uint32_t&r1,uint32_t&r2,uint32_t&r3){
    asm volatile("ldmatrix.sync.aligned.m8n8.x4.trans.shared.b16 {%0,%1,%2,%3}, [%4];\n"
        : "=r"(r0),"=r"(r1),"=r"(r2),"=r"(r3) : "r"(a));
}
__device__ __forceinline__ void mma16(float* c, uint32_t a0,uint32_t a1,uint32_t a2,uint32_t a3,
                                      uint32_t b0,uint32_t b1){
    asm volatile("mma.sync.aligned.m16n8k16.row.col.f32.bf16.bf16.f32 "
        "{%0,%1,%2,%3}, {%4,%5,%6,%7}, {%8,%9}, {%0,%1,%2,%3};\n"
        : "+f"(c[0]),"+f"(c[1]),"+f"(c[2]),"+f"(c[3])
        : "r"(a0),"r"(a1),"r"(a2),"r"(a3),"r"(b0),"r"(b1));
}
__device__ __forceinline__ void split2(float x, bf16& h, bf16& l){
    h = __float2bfloat16(x);
    l = __float2bfloat16(x - __bfloat162float(h));
}

// ---- bulk TMA + mbarrier ----
__device__ __forceinline__ void bulk_ld(uint32_t dst, const void* src, uint32_t bytes, uint32_t mbar){
    asm volatile("cp.async.bulk.shared::cta.global.mbarrier::complete_tx::bytes [%0], [%1], %2, [%3];\n"
        :: "r"(dst), "l"(src), "r"(bytes), "r"(mbar) : "memory");
}
__device__ __forceinline__ void mbar_init(uint32_t mbar, uint32_t cnt){
    asm volatile("mbarrier.init.shared.b64 [%0], %1;\n" :: "r"(mbar), "r"(cnt) : "memory");
}
__device__ __forceinline__ void mbar_expect(uint32_t mbar, uint32_t tx){
    asm volatile("mbarrier.arrive.expect_tx.shared.b64 _, [%0], %1;\n" :: "r"(mbar), "r"(tx) : "memory");
}
__device__ __forceinline__ void mbar_wait(uint32_t mbar, uint32_t parity){
    asm volatile("{\n\t.reg .pred P;\n\t"
        "W%=:\n\t"
        "mbarrier.try_wait.parity.acquire.cta.shared::cta.b64 P, [%0], %1, 0x989680;\n\t"
        "@!P bra W%=;\n\t}\n"
        :: "r"(mbar), "r"(parity) : "memory");
}

// ---------------- split f32 -> tile-major pre-swizzled bf16 hi/lo ----------------
__global__ void split_tile(const float* __restrict__ x, bf16* __restrict__ th,
                           bf16* __restrict__ tl, int n4)
{
    int i = blockIdx.x*blockDim.x + threadIdx.x;
    if (i >= n4) return;
    const int r = i >> 8, c4 = (i & 255) << 2;
    float4 v = reinterpret_cast<const float4*>(x)[i];
    bf16 h0,l0,h1,l1,h2,l2,h3,l3;
    split2(v.x,h0,l0); split2(v.y,h1,l1); split2(v.z,h2,l2); split2(v.w,h3,l3);
    const size_t tile = (size_t)((r>>7)*16 + (c4>>6)) * 16384;  // bytes
    const uint32_t off = SWZ(((r&127)<<7) + ((c4&63)<<1));
    char* dh = (char*)th + tile + off;
    char* dl = (char*)tl + tile + off;
    *reinterpret_cast<bf162*>(dh)   = __halves2bfloat162(h0,h1);
    *reinterpret_cast<bf162*>(dh+4) = __halves2bfloat162(h2,h3);
    *reinterpret_cast<bf162*>(dl)   = __halves2bfloat162(l0,l1);
    *reinterpret_cast<bf162*>(dl+4) = __halves2bfloat162(l2,l3);
}

// ============================================================
// Projection GEMM (NT, mma.sync, bulk-TMA staged): C[128,128] tile,
// BK=64, 2 stages x 64KB, 8 warps (64x32 warp tiles), bf16x3 split.
// outmode: 0 = bf16 row-major split, 1 = bf16 tile-major swizzled split,
//          2 = f32 + bias + resid
// ============================================================
#define PR_STAGE 65536
#define PR_SMEM  (128 + 2*PR_STAGE)

__global__ __launch_bounds__(256,1) void proj_kernel(
    const bf16* __restrict__ Ahg, const bf16* __restrict__ Alg,
    const bf16* __restrict__ Bhg, const bf16* __restrict__ Blg,
    const float* __restrict__ bias, const float* __restrict__ resid,
    bf16* __restrict__ outh, bf16* __restrict__ outl, float* __restrict__ outf,
    int outmode)
{
    extern __shared__ __align__(128) char sm_[];
    const int tid = threadIdx.x, lane = tid&31, warp = tid>>5;
    const int n0 = blockIdx.x, m0 = blockIdx.y;
    const uint32_t sb = s2u(sm_);
    const uint32_t dat = sb + 128;

    if (tid == 0){
        mbar_init(sb+0, 1);
        mbar_init(sb+8, 1);
#pragma unroll
        for (int p = 0; p < 2; p++){
            const uint32_t mb = sb + p*8;
            const uint32_t buf = dat + p*PR_STAGE;
            mbar_expect(mb, PR_STAGE);
            bulk_ld(buf,        (const char*)Ahg + (size_t)(m0*16+p)*16384, 16384, mb);
            bulk_ld(buf+16384,  (const char*)Alg + (size_t)(m0*16+p)*16384, 16384, mb);
            bulk_ld(buf+32768,  (const char*)Bhg + (size_t)(n0*16+p)*16384, 16384, mb);
            bulk_ld(buf+49152,  (const char*)Blg + (size_t)(n0*16+p)*16384, 16384, mb);
        }
    }
    __syncthreads();

    const int wm = (warp>>2)*64, wn = (warp&3)*32;
    float acc[4][4][4] = {};

    for (int kt = 0; kt < 16; kt++){
        const int b = kt & 1;
        mbar_wait(sb + b*8, (kt>>1)&1);
        const uint32_t buf = dat + b*PR_STAGE;
#pragma unroll
        for (int ks = 0; ks < 4; ks++){
            uint32_t bhf[4][2], blf[4][2];
#pragma unroll
            for (int p = 0; p < 2; p++){
                const uint32_t roff = (uint32_t)(wn + p*16 + (lane&7) + ((lane>>4)&1)*8)*128
                                      + ks*32 + ((lane>>3)&1)*16;
                ldm4(buf + 32768 + SWZ(roff), bhf[2*p][0], bhf[2*p][1], bhf[2*p+1][0], bhf[2*p+1][1]);
                ldm4(buf + 49152 + SWZ(roff), blf[2*p][0], blf[2*p][1], blf[2*p+1][0], blf[2*p+1][1]);
            }
#pragma unroll
            for (int mi = 0; mi < 4; mi++){
                const uint32_t roff = (uint32_t)(wm + mi*16 + (lane&15))*128
                                      + ks*32 + ((lane>>4)&1)*16;
                uint32_t a0,a1,a2,a3, l0,l1,l2,l3;
                ldm4(buf +         SWZ(roff), a0,a1,a2,a3);
                ldm4(buf + 16384 + SWZ(roff), l0,l1,l2,l3);
#pragma unroll
                for (int ni = 0; ni < 4; ni++){
                    mma16(acc[mi][ni], a0,a1,a2,a3, bhf[ni][0], bhf[ni][1]);
                    mma16(acc[mi][ni], a0,a1,a2,a3, blf[ni][0], blf[ni][1]);
                    mma16(acc[mi][ni], l0,l1,l2,l3, bhf[ni][0], bhf[ni][1]);
                }
            }
        }
        __syncthreads();
        if (tid == 0 && kt+2 < 16){
            const uint32_t mb = sb + b*8;
            mbar_expect(mb, PR_STAGE);
            bulk_ld(buf,        (const char*)Ahg + (size_t)(m0*16+kt+2)*16384, 16384, mb);
            bulk_ld(buf+16384,  (const char*)Alg + (size_t)(m0*16+kt+2)*16384, 16384, mb);
            bulk_ld(buf+32768,  (const char*)Bhg + (size_t)(n0*16+kt+2)*16384, 16384, mb);
            bulk_ld(buf+49152,  (const char*)Blg + (size_t)(n0*16+kt+2)*16384, 16384, mb);
        }
    }

    // epilogue
    const int bm = m0*128, bn = n0*128;
    const int g = lane>>2, tg = lane&3;
#pragma unroll
    for (int mi=0; mi<4; mi++)
#pragma unroll
    for (int ni=0; ni<4; ni++){
        const int r0 = bm+wm+mi*16+g;
        const int c  = bn+wn+ni*8+tg*2;
        const float2 bv = *reinterpret_cast<const float2*>(&bias[c]);
        const float x0=acc[mi][ni][0]+bv.x, x1=acc[mi][ni][1]+bv.y;
        const float x2=acc[mi][ni][2]+bv.x, x3=acc[mi][ni][3]+bv.y;
        if (outmode == 2){
            const float2 q0 = *reinterpret_cast<const float2*>(&resid[(size_t)r0*Dq + c]);
            const float2 q1 = *reinterpret_cast<const float2*>(&resid[(size_t)(r0+8)*Dq + c]);
            *reinterpret_cast<float2*>(&outf[(size_t)r0*Dq+c])     = make_float2(x0+q0.x, x1+q0.y);
            *reinterpret_cast<float2*>(&outf[(size_t)(r0+8)*Dq+c]) = make_float2(x2+q1.x, x3+q1.y);
        } else if (outmode == 1){
            // tile-major swizzled split
            bf16 h0,l0,h1,l1;
#pragma unroll
            for (int hh = 0; hh < 2; hh++){
                const int rr = r0 + hh*8;
                const size_t tb = ((size_t)(rr>>7)*16 + (c>>6)) * 16384;
                const uint32_t off = SWZ(((rr&127)<<7) + ((c&63)<<1));
                const float y0 = hh ? x2 : x0;
                const float y1 = hh ? x3 : x1;
                split2(y0,h0,l0); split2(y1,h1,l1);
                *reinterpret_cast<bf162*>((char*)outh + tb + off) = __halves2bfloat162(h0,h1);
                *reinterpret_cast<bf162*>((char*)outl + tb + off) = __halves2bfloat162(l0,l1);
            }
        } else {
            bf16 h0,l0,h1,l1;
            split2(x0,h0,l0); split2(x1,h1,l1);
            *reinterpret_cast<bf162*>(&outh[(size_t)r0*Dq+c]) = __halves2bfloat162(h0,h1);
            *reinterpret_cast<bf162*>(&outl[(size_t)r0*Dq+c]) = __halves2bfloat162(l0,l1);
            split2(x2,h0,l0); split2(x3,h1,l1);
            *reinterpret_cast<bf162*>(&outh[(size_t)(r0+8)*Dq+c]) = __halves2bfloat162(h0,h1);
            *reinterpret_cast<bf162*>(&outl[(size_t)(r0+8)*Dq+c]) = __halves2bfloat162(l0,l1);
        }
    }
}

// ============================================================
// Scores (bulk-TMA): per (b,h) E[q,k] = exp((q.k)/8) + partial row sums.
// Q/K tiles are tile-major swizzled; one 64KB bulk load, K=64, no pipeline.
// ============================================================
#define SC_SMEM (128 + 65536)

__global__ __launch_bounds__(256) void scores_kernel(float* __restrict__ scores)
{
    extern __shared__ __align__(128) char sm_[];
    const int bh = blockIdx.z, b = bh>>4, h = bh&15;
    const int tid = threadIdx.x, lane = tid&31, warp = tid>>5;
    const int bm = blockIdx.y*128, bn = blockIdx.x*128;
    const uint32_t sb = s2u(sm_);
    const uint32_t dat = sb + 128;

    const size_t atile = ((size_t)(b*16 + blockIdx.y)*16 + h) * 16384;  // bytes
    const size_t btile = ((size_t)(b*16 + blockIdx.x)*16 + h) * 16384;

    if (tid == 0){
        mbar_init(sb, 1);
    }
    __syncthreads();
    if (tid == 0){
        mbar_expect(sb, 65536);
        bulk_ld(dat,        (const char*)g_qh + atile, 16384, sb);
        bulk_ld(dat+16384,  (const char*)g_ql + atile, 16384, sb);
        bulk_ld(dat+32768,  (const char*)g_kh + btile, 16384, sb);
        bulk_ld(dat+49152,  (const char*)g_kl + btile, 16384, sb);
    }

    const int wm = (warp>>2)*64, wn = (warp&3)*32;
    float acc[4][4][4] = {};

    mbar_wait(sb, 0);

#pragma unroll
    for (int ks = 0; ks < 4; ks++){
        uint32_t bhf[4][2], blf[4][2];
#pragma unroll
        for (int p = 0; p < 2; p++){
            const uint32_t roff = (uint32_t)(wn + p*16 + (lane&7) + ((lane>>4)&1)*8)*128
                                  + ks*32 + ((lane>>3)&1)*16;
            ldm4(dat + 32768 + SWZ(roff), bhf[2*p][0], bhf[2*p][1], bhf[2*p+1][0], bhf[2*p+1][1]);
            ldm4(dat + 49152 + SWZ(roff), blf[2*p][0], blf[2*p][1], blf[2*p+1][0], blf[2*p+1][1]);
        }
#pragma unroll
        for (int mi = 0; mi < 4; mi++){
            const uint32_t roff = (uint32_t)(wm + mi*16 + (lane&15))*128
                                  + ks*32 + ((lane>>4)&1)*16;
            uint32_t a0,a1,a2,a3, l0,l1,l2,l3;
            ldm4(dat +         SWZ(roff), a0,a1,a2,a3);
            ldm4(dat + 16384 + SWZ(roff), l0,l1,l2,l3);
#pragma unroll
            for (int ni = 0; ni < 4; ni++){
                mma16(acc[mi][ni], a0,a1,a2,a3, bhf[ni][0], bhf[ni][1]);
                mma16(acc[mi][ni], a0,a1,a2,a3, blf[ni][0], blf[ni][1]);
                mma16(acc[mi][ni], l0,l1,l2,l3, bhf[ni][0], bhf[ni][1]);
            }
        }
    }

    __shared__ float psum[128][4];
    float* C = scores + (size_t)bh*Sq*Sq;
    const int wm2=wm, wn2=wn, g=lane>>2, tg=lane&3;
    const int wnidx = warp & 3;
#pragma unroll
    for (int mi=0; mi<4; mi++){
        float s0 = 0.f, s1 = 0.f;
#pragma unroll
        for (int ni=0; ni<4; ni++){
            const int r0 = bm+wm2+mi*16+g;
            const int c  = bn+wn2+ni*8+tg*2;
            const float e0 = __expf(acc[mi][ni][0]*0.125f);
            const float e1 = __expf(acc[mi][ni][1]*0.125f);
            const float e2 = __expf(acc[mi][ni][2]*0.125f);
            const float e3 = __expf(acc[mi][ni][3]*0.125f);
            *reinterpret_cast<float2*>(&C[(size_t)r0*Sq+c])     = make_float2(e0, e1);
            *reinterpret_cast<float2*>(&C[(size_t)(r0+8)*Sq+c]) = make_float2(e2, e3);
            s0 += e0 + e1;
            s1 += e2 + e3;
        }
        s0 += __shfl_xor_sync(0xffffffffu, s0, 1);
        s0 += __shfl_xor_sync(0xffffffffu, s0, 2);
        s1 += __shfl_xor_sync(0xffffffffu, s1, 1);
        s1 += __shfl_xor_sync(0xffffffffu, s1, 2);
        if (tg == 0){
            psum[wm2+mi*16+g][wnidx]   = s0;
            psum[wm2+mi*16+g+8][wnidx] = s1;
        }
    }
    __syncthreads();
    if (tid < 128){
        const float t = psum[tid][0] + psum[tid][1] + psum[tid][2] + psum[tid][3];
        g_psum[((size_t)bh*16 + blockIdx.x)*Sq + bm + tid] = t;
    }
}

// ============================================================
// PV + normalize; ctx written tile-major swizzled for the O projection
// ============================================================
__global__ __launch_bounds__(256,2) void av_kernel(float* __restrict__ scores)
{
    __shared__ char smem[2*16896];
    const int bh = blockIdx.z, b = bh>>4, h = bh&15;
    float* P = scores + (size_t)bh*Sq*Sq;
    const bf16* Vhg = g_vh + (size_t)b*Sq*Dq + h*DHq;
    const bf16* Vlg = g_vl + (size_t)b*Sq*Dq + h*DHq;
    const int tid = threadIdx.x, lane = tid&31, warp = tid>>5;
    const int wm = (warp>>1)*32, wn = (warp&1)*32;
    const int bm = blockIdx.y*128;
    const uint32_t sb = s2u(smem);

    float acc[2][4][4] = {};

    const int va = tid>>7, vr = (tid>>3)&15, vc = tid&7;
    const bf16* vsrc = va ? Vlg : Vhg;
    const int pr = tid>>2, pq = (tid&3)*4;

    float sum0 = 0.f, sum1 = 0.f;
#pragma unroll
    for (int t = 0; t < 16; t++){
        sum0 += g_psum[((size_t)bh*16 + t)*Sq + bm + pr];
        sum1 += g_psum[((size_t)bh*16 + t)*Sq + bm + 64 + pr];
    }
    const float inv0 = 1.0f / sum0;
    const float inv1 = 1.0f / sum1;

    float4 p0, p1, n0, n1;
    p0 = *reinterpret_cast<const float4*>(&P[(size_t)(bm + pr)*Sq + pq]);
    p1 = *reinterpret_cast<const float4*>(&P[(size_t)(bm + 64 + pr)*Sq + pq]);
    {
        uint32_t s = sb + 12288u + (uint32_t)(va*2304 + vr*144 + vc*16);
        cpa16(s, vsrc + (size_t)vr*Dq + vc*8);
        cpcommit();
    }

    for (int kt = 0; kt < 128; kt++){
        const int s = kt&1;
        const uint32_t st = sb + (uint32_t)(s*16896);
        {
            p0.x *= inv0; p0.y *= inv0; p0.z *= inv0; p0.w *= inv0;
            p1.x *= inv1; p1.y *= inv1; p1.z *= inv1; p1.w *= inv1;
            *reinterpret_cast<float4*>(&P[(size_t)(bm + pr)*Sq + kt*16 + pq])      = p0;
            *reinterpret_cast<float4*>(&P[(size_t)(bm + 64 + pr)*Sq + kt*16 + pq]) = p1;

            bf16 h0,l0,h1,l1,h2,l2,h3,l3;
            char* base = smem + s*16896;
            split2(p0.x,h0,l0); split2(p0.y,h1,l1); split2(p0.z,h2,l2); split2(p0.w,h3,l3);
            *reinterpret_cast<bf162*>(base + pr*48 + pq*2)          = __halves2bfloat162(h0,h1);
            *reinterpret_cast<bf162*>(base + pr*48 + pq*2 + 4)      = __halves2bfloat162(h2,h3);
            *reinterpret_cast<bf162*>(base + 6144 + pr*48 + pq*2)   = __halves2bfloat162(l0,l1);
            *reinterpret_cast<bf162*>(base + 6144 + pr*48 + pq*2+4) = __halves2bfloat162(l2,l3);
            split2(p1.x,h0,l0); split2(p1.y,h1,l1); split2(p1.z,h2,l2); split2(p1.w,h3,l3);
            *reinterpret_cast<bf162*>(base + (pr+64)*48 + pq*2)          = __halves2bfloat162(h0,h1);
            *reinterpret_cast<bf162*>(base + (pr+64)*48 + pq*2 + 4)      = __halves2bfloat162(h2,h3);
            *reinterpret_cast<bf162*>(base + 6144 + (pr+64)*48 + pq*2)   = __halves2bfloat162(l0,l1);
            *reinterpret_cast<bf162*>(base + 6144 + (pr+64)*48 + pq*2+4) = __halves2bfloat162(l2,l3);
        }
        if (kt+1 < 128){
            const int k0 = (kt+1)*16;
            n0 = *reinterpret_cast<const float4*>(&P[(size_t)(bm + pr)*Sq + k0 + pq]);
            n1 = *reinterpret_cast<const float4*>(&P[(size_t)(bm + 64 + pr)*Sq + k0 + pq]);
        }
        cpwait();
        __syncthreads();
        if (kt+1 < 128){
            const int k0 = (kt+1)*16;
            uint32_t sv = sb + (uint32_t)((s^1)*16896) + 12288u + (uint32_t)(va*2304 + vr*144 + vc*16);
            cpa16(sv, vsrc + (size_t)(k0+vr)*Dq + vc*8);
            cpcommit();
        }
        uint32_t bhf[4][2], blf[4][2];
#pragma unroll
        for (int p = 0; p < 2; p++){
            uint32_t addr = st + 12288u +
                (uint32_t)(((lane>>3)&1)*8*144 + (lane&7)*144 + (wn + p*16 + ((lane>>4)&1)*8)*2);
            ldm4t(addr,        bhf[2*p][0], bhf[2*p][1], bhf[2*p+1][0], bhf[2*p+1][1]);
            ldm4t(addr + 2304, blf[2*p][0], blf[2*p][1], blf[2*p+1][0], blf[2*p+1][1]);
        }
#pragma unroll
        for (int mi = 0; mi < 2; mi++){
            uint32_t aaddr = st + (uint32_t)((wm + mi*16 + (lane&15))*48 + ((lane>>4)&1)*16);
            uint32_t a0,a1,a2,a3, l0,l1,l2,l3;
            ldm4(aaddr,        a0,a1,a2,a3);
            ldm4(aaddr + 6144, l0,l1,l2,l3);
#pragma unroll
            for (int ni = 0; ni < 4; ni++){
                mma16(acc[mi][ni], a0,a1,a2,a3, bhf[ni][0], bhf[ni][1]);
                mma16(acc[mi][ni], a0,a1,a2,a3, blf[ni][0], blf[ni][1]);
                mma16(acc[mi][ni], l0,l1,l2,l3, bhf[ni][0], bhf[ni][1]);
            }
        }
        p0 = n0; p1 = n1;
    }

    // epilogue: ctx -> tile-major pre-swizzled layout (tile col index == head)
    const int g = lane>>2, tg = lane&3;
#pragma unroll
    for (int mi = 0; mi < 2; mi++)
#pragma unroll
    for (int ni = 0; ni < 4; ni++){
        const int r0 = bm + wm + mi*16 + g;
        const int c  = wn + ni*8 + tg*2;
#pragma unroll
        for (int hh = 0; hh < 2; hh++){
            const int grow = b*Sq + r0 + hh*8;
            const size_t tb = ((size_t)((grow>>7)*16 + h)) * 16384;
            const uint32_t off = SWZ(((grow&127)<<7) + (c<<1));
            const float x0 = acc[mi][ni][hh*2+0];
            const float x1 = acc[mi][ni][hh*2+1];
            bf16 h0,l0,h1,l1;
            split2(x0,h0,l0); split2(x1,h1,l1);
            *reinterpret_cast<bf162*>((char*)g_pch + tb + off) = __halves2bfloat162(h0,h1);
            *reinterpret_cast<bf162*>((char*)g_pcl + tb + off) = __halves2bfloat162(l0,l1);
        }
    }
}

// ============================================================
// LayerNorm per row of g_y -> d_out
// ============================================================
__global__ void ln_kernel(const float* __restrict__ gamma,
                          const float* __restrict__ beta,
                          float* __restrict__ out)
{
    const size_t row = blockIdx.x;
    const float4* y = reinterpret_cast<const float4*>(g_y + row * (size_t)Dq);
    float4* o = reinterpret_cast<float4*>(out + row * (size_t)Dq);
    const int tid = threadIdx.x;
    __shared__ float sm[8], sm2[8];

    float4 v = y[tid];
    float s  = v.x + v.y + v.z + v.w;
    float s2 = v.x*v.x + v.y*v.y + v.z*v.z + v.w*v.w;
#pragma unroll
    for (int o2 = 16; o2 > 0; o2 >>= 1) {
        s  += __shfl_xor_sync(0xffffffffu, s,  o2);
        s2 += __shfl_xor_sync(0xffffffffu, s2, o2);
    }
    if ((tid & 31) == 0) { sm[tid>>5] = s; sm2[tid>>5] = s2; }
    __syncthreads();
    float ts = 0.f, ts2 = 0.f;
#pragma unroll
    for (int w = 0; w < 8; w++) { ts += sm[w]; ts2 += sm2[w]; }
    const float mean = ts * (1.0f/Dq);
    const float var  = ts2 * (1.0f/Dq) - mean*mean;
    const float rstd = rsqrtf(var + 1e-6f);

    const float4 gg = reinterpret_cast<const float4*>(gamma)[tid];
    const float4 bb = reinterpret_cast<const float4*>(beta)[tid];
    float4 r;
    r.x = (v.x - mean) * rstd * gg.x + bb.x;
    r.y = (v.y - mean) * rstd * gg.y + bb.y;
    r.z = (v.z - mean) * rstd * gg.z + bb.z;
    r.w = (v.w - mean) * rstd * gg.w + bb.w;
    o[tid] = r;
}

// ============================================================
extern "C" void kernel_launch(void* const* d_in, const int* in_sizes, int n_in,
                              void* d_out, int out_size)
{
    const float* Q     = (const float*)d_in[0];
    const float* K     = (const float*)d_in[1];
    const float* V     = (const float*)d_in[2];
    const float* Wq    = (const float*)d_in[3];
    const float* bq    = (const float*)d_in[4];
    const float* Wk    = (const float*)d_in[5];
    const float* bk    = (const float*)d_in[6];
    const float* Wv    = (const float*)d_in[7];
    const float* bv    = (const float*)d_in[8];
    const float* Wo    = (const float*)d_in[9];
    const float* bo    = (const float*)d_in[10];
    const float* gamma = (const float*)d_in[11];
    const float* beta  = (const float*)d_in[12];

    float* out    = (float*)d_out;
    float* scores = out + OUT_OFF;

    bf16 *pah, *pal, *pwh, *pwl, *pch, *pcl;
    bf16 *qh, *ql, *kh, *kl, *vh, *vl;
    float* gy;
    cudaGetSymbolAddress((void**)&pah, g_pah);
    cudaGetSymbolAddress((void**)&pal, g_pal);
    cudaGetSymbolAddress((void**)&pwh, g_pwh);
    cudaGetSymbolAddress((void**)&pwl, g_pwl);
    cudaGetSymbolAddress((void**)&pch, g_pch);
    cudaGetSymbolAddress((void**)&pcl, g_pcl);
    cudaGetSymbolAddress((void**)&qh, g_qh); cudaGetSymbolAddress((void**)&ql, g_ql);
    cudaGetSymbolAddress((void**)&kh, g_kh); cudaGetSymbolAddress((void**)&kl, g_kl);
    cudaGetSymbolAddress((void**)&vh, g_vh); cudaGetSymbolAddress((void**)&vl, g_vl);
    cudaGetSymbolAddress((void**)&gy, g_y);

    static bool attr_set = false;
    if (!attr_set){
        cudaFuncSetAttribute(proj_kernel,   cudaFuncAttributeMaxDynamicSharedMemorySize, PR_SMEM);
        cudaFuncSetAttribute(scores_kernel, cudaFuncAttributeMaxDynamicSharedMemorySize, SC_SMEM);
        attr_set = true;
    }

    dim3 blk(256);

    // splits into tile-major pre-swizzled layouts
    split_tile<<<NELEM/4/256, 256>>>(Q, pah + 0*(size_t)NELEM, pal + 0*(size_t)NELEM, NELEM/4);
    split_tile<<<NELEM/4/256, 256>>>(K, pah + 1*(size_t)NELEM, pal + 1*(size_t)NELEM, NELEM/4);
    split_tile<<<NELEM/4/256, 256>>>(V, pah + 2*(size_t)NELEM, pal + 2*(size_t)NELEM, NELEM/4);
    split_tile<<<WN/4/256, 256>>>(Wq, pwh + 0*(size_t)WN, pwl + 0*(size_t)WN, WN/4);
    split_tile<<<WN/4/256, 256>>>(Wk, pwh + 1*(size_t)WN, pwl + 1*(size_t)WN, WN/4);
    split_tile<<<WN/4/256, 256>>>(Wv, pwh + 2*(size_t)WN, pwl + 2*(size_t)WN, WN/4);
    split_tile<<<WN/4/256, 256>>>(Wo, pwh + 3*(size_t)WN, pwl + 3*(size_t)WN, WN/4);

    // projections: q/k -> tile-major (mode 1), v -> row-major (mode 0)
    dim3 gP(8, 32);
    proj_kernel<<<gP, blk, PR_SMEM>>>(pah+0*(size_t)NELEM, pal+0*(size_t)NELEM,
                                      pwh+0*(size_t)WN, pwl+0*(size_t)WN,
                                      bq, nullptr, qh, ql, nullptr, 1);
    proj_kernel<<<gP, blk, PR_SMEM>>>(pah+1*(size_t)NELEM, pal+1*(size_t)NELEM,
                                      pwh+1*(size_t)WN, pwl+1*(size_t)WN,
                                      bk, nullptr, kh, kl, nullptr, 1);
    proj_kernel<<<gP, blk, PR_SMEM>>>(pah+2*(size_t)NELEM, pal+2*(size_t)NELEM,
                                      pwh+2*(size_t)WN, pwl+2*(size_t)WN,
                                      bv, nullptr, vh, vl, nullptr, 0);

    // scores (bulk-TMA) -> E = exp(S/8) + partial row sums
    dim3 gSc(Sq/128, Sq/128, Bq*Hq);
    scores_kernel<<<gSc, blk, SC_SMEM>>>(scores);

    // PV + normalization + normalized-P writeback; ctx -> tile-major
    dim3 gAv(1, Sq/128, Bq*Hq);
    av_kernel<<<gAv, blk>>>(scores);

    // O projection + bias + residual -> g_y
    proj_kernel<<<gP, blk, PR_SMEM>>>(pch, pcl, pwh+3*(size_t)WN, pwl+3*(size_t)WN,
                                      bo, Q, nullptr, nullptr, gy, 2);

    ln_kernel<<<(unsigned)Mq, blk>>>(gamma, beta, out);
}